// round 11
// baseline (speedup 1.0000x reference)
#include <cuda_runtime.h>
#include <cuda_fp16.h>
#include <cstdint>

// Problem constants
#define BATCH 256
#define CCH   64
#define TLEN  4096
#define NBLK  4
#define TOUT  2048
#define JC    60
#define NCHUNK 35
#define NTH   256

// ---- SMEM byte layout (total 114832, 2 CTAs/SM) ----
// REG  [0, 34816):      W1 fp16 [128][272B] (GEMM1) / W3 fp16 [64][272B] (GEMM3)
//                       + SD fp32 [64][68f] at byte 17408 (epilogue 3 only)
// W2   [34816, 44032):  fp16 [64][144B]
// P16  [44032, 62464):  fp16 [128][144B]   (own buffer -> no GEMM1/epi1 barrier)
// G32  [62464, 96256):  fp32 rows 1..128, stride 66 floats; GD16 [64][272B] overlays
// G16  [96256, 114832): fp16 [129][144B]
#define W1_STRB 272
#define P_STRB  144
#define P_STRW  36
#define W2_OFFB 34816
#define P16_OFFB 44032
#define SD_OFFF 4352
#define SD_STRF 68
#define G32_OFFF 15616
#define G32_STRF 66
#define GD_OFFB 62464
#define GD_STRW 68
#define G16_OFFB 96256
#define G16_OFFH 48128
#define G16_STRB 144
#define G16_STRH 72
#define G16_STRW 36
#define SMEM_BYTES 114832

// Pre-converted fp16 weights in SMEM row layout
__device__ __align__(16) __half wpre1[NBLK][128 * 136];  // sig/gate interleaved
__device__ __align__(16) __half wpre2[NBLK][64 * 72];    // out_w
__device__ __align__(16) __half wpre3[64 * 136];         // dil_w

__global__ void __launch_bounds__(256)
prep_weights(const float* __restrict__ sig_w, const float* __restrict__ gate_w,
             const float* __restrict__ out_w, const float* __restrict__ dil_w)
{
    int tid0 = blockIdx.x * 256 + threadIdx.x;
    int nth  = gridDim.x * 256;
    for (int idx = tid0; idx < NBLK * 128 * 128; idx += nth) {
        int iblk = idx >> 14, r = (idx >> 7) & 127, k = idx & 127;
        int wn = r >> 5, rr = r & 31;
        int h  = 16 * wn + (rr & 15);
        const float* src = (rr < 16 ? sig_w : gate_w) + iblk * 8192;
        wpre1[iblk][r * 136 + k] = __float2half(src[h * 128 + (k & 63) * 2 + (k >> 6)]);
    }
    for (int idx = tid0; idx < NBLK * 64 * 64; idx += nth) {
        int iblk = idx >> 12, c = (idx >> 6) & 63, h = idx & 63;
        wpre2[iblk][c * 72 + h] = __float2half(out_w[iblk * 4096 + c * 64 + h]);
    }
    for (int idx = tid0; idx < 64 * 128; idx += nth) {
        int cc = idx >> 7, k = idx & 127;
        wpre3[cc * 136 + k] = __float2half(dil_w[cc * 128 + (k & 63) * 2 + (k >> 6)]);
    }
}

__device__ __forceinline__ uint32_t packh2(float lo, float hi) {
    __half2 h = __floats2half2_rn(lo, hi);
    return *reinterpret_cast<uint32_t*>(&h);
}
__device__ __forceinline__ float sigm(float v) { return 1.f / (1.f + __expf(-v)); }
__device__ __forceinline__ void mma16(float d[4], const uint32_t a[4],
                                      uint32_t b0, uint32_t b1) {
    asm volatile(
        "mma.sync.aligned.m16n8k16.row.col.f32.f16.f16.f32 "
        "{%0,%1,%2,%3}, {%4,%5,%6,%7}, {%8,%9}, {%0,%1,%2,%3};"
        : "+f"(d[0]), "+f"(d[1]), "+f"(d[2]), "+f"(d[3])
        : "r"(a[0]), "r"(a[1]), "r"(a[2]), "r"(a[3]), "r"(b0), "r"(b1));
}
__device__ __forceinline__ void ldm4(uint32_t r[4], uint32_t addr) {
    asm volatile("ldmatrix.sync.aligned.m8n8.x4.shared.b16 {%0,%1,%2,%3}, [%4];"
        : "=r"(r[0]), "=r"(r[1]), "=r"(r[2]), "=r"(r[3]) : "r"(addr));
}
__device__ __forceinline__ void cp16(uint32_t dst, const __half* src) {
    asm volatile("cp.async.cg.shared.global [%0], [%1], 16;"
        :: "r"(dst), "l"(__cvta_generic_to_global(src)));
}
#define CP_COMMIT() asm volatile("cp.async.commit_group;" ::: "memory")
#define CP_WAIT0()  asm volatile("cp.async.wait_group 0;" ::: "memory")

__global__ void __launch_bounds__(NTH, 2)
wavenet_h16_kernel(const float* __restrict__ x,
                   const float* __restrict__ sig_b, const float* __restrict__ gate_b,
                   const float* __restrict__ out_b,
                   const float* __restrict__ skip_w, const float* __restrict__ skip_b,
                   const float* __restrict__ dil_b,
                   float* __restrict__ out)
{
    extern __shared__ float sm[];
    uint32_t* P16u = (uint32_t*)((char*)sm + P16_OFFB);
    float*    SD   = sm + SD_OFFF;
    float*    G    = sm + G32_OFFF;          // rows 1..128 at (r-1)*66
    uint32_t* GDu  = (uint32_t*)((char*)sm + GD_OFFB);
    __half*   G16h = (__half*)sm + G16_OFFH;
    uint32_t* G16u = (uint32_t*)((char*)sm + G16_OFFB);

    const uint32_t smem_s = (uint32_t)__cvta_generic_to_shared(sm);

    const int tid = threadIdx.x;
    const int w   = tid >> 5;      // 0..7
    const int l   = tid & 31;
    const int g   = l >> 2;
    const int t   = l & 3;
    const int wm  = w >> 2;        // GEMM1: m 64-block (0..1)
    const int wn  = w & 3;         // GEMM1: n 32-block (0..3) = channels 16wn..+16
    const int wm2 = w >> 1;        // GEMM2: m 32-block (0..3)
    const int wn2 = w & 1;         // GEMM2: n 32-block (0..1)
    const int matLo = (l >> 3) & 1;
    const int matHi = l >> 4;
    const int lmrow = l & 7;

    const int b     = blockIdx.y;
    const int chunk = blockIdx.x;
    const int j0    = chunk * JC;
    const int tbase = 2 * j0 - 5;

    // ---- prologue: stage W1(0)+W2(0) via cp.async, overlapped with x-load ----
    for (int idx = tid; idx < 2176; idx += NTH)
        cp16(smem_s + idx * 16, &wpre1[0][0] + idx * 8);
    for (int idx = tid; idx < 576; idx += NTH)
        cp16(smem_s + W2_OFFB + idx * 16, &wpre2[0][0] + idx * 8);
    CP_COMMIT();

    // ---- load x tile into G32 (rows 1..128) and G16 (rows 0..128) ----
    const float* xb = x + (size_t)b * CCH * TLEN;
    for (int c = w; c < CCH; c += 8) {
        const float* xc = xb + c * TLEN;
        for (int q = l; q < 129; q += 32) {
            int tt = tbase + q - 1;
            float v = (tt >= 0 && tt < TLEN) ? xc[tt] : 0.f;
            if (q >= 1) G[(q - 1) * G32_STRF + c] = v;
            G16h[q * G16_STRH + c] = __float2half(v);
        }
    }
    CP_WAIT0();
    __syncthreads();

    // ldmatrix base addresses
    uint32_t aAdr1[4];
    #pragma unroll
    for (int mi = 0; mi < 4; mi++)
        aAdr1[mi] = smem_s + G16_OFFB
                  + (64 * wm + 16 * mi + matLo * 8 + lmrow) * G16_STRB + matHi * 16;
    uint32_t bAdr1[2];
    #pragma unroll
    for (int p = 0; p < 2; p++)
        bAdr1[p] = smem_s + (32 * wn + 16 * p + matHi * 8 + lmrow) * W1_STRB + matLo * 16;
    uint32_t aAdr2[2];
    #pragma unroll
    for (int mi = 0; mi < 2; mi++)
        aAdr2[mi] = smem_s + P16_OFFB
                  + (32 * wm2 + 16 * mi + matLo * 8 + lmrow) * P_STRB + matHi * 16;
    uint32_t bAdr2[2];
    #pragma unroll
    for (int p = 0; p < 2; p++)
        bAdr2[p] = smem_s + W2_OFFB + (32 * wn2 + 16 * p + matHi * 8 + lmrow) * P_STRB + matLo * 16;

    // ================= 4 residual blocks (3 barriers each) =================
    for (int iblk = 0; iblk < NBLK; iblk++) {
        // ---- GEMM1: D[128m][128n], warp tile 64m x 32n ----
        float acc[4][4][4];
        #pragma unroll
        for (int mi = 0; mi < 4; mi++)
            #pragma unroll
            for (int ni = 0; ni < 4; ni++)
                #pragma unroll
                for (int q = 0; q < 4; q++) acc[mi][ni][q] = 0.f;

        #pragma unroll
        for (int kt = 0; kt < 8; kt++) {
            const uint32_t kOffA = (kt >> 2) * G16_STRB + (kt & 3) * 32;
            const uint32_t kOffB = kt * 32;
            uint32_t a[4][4], b0[4], b1[4];
            #pragma unroll
            for (int mi = 0; mi < 4; mi++) ldm4(a[mi], aAdr1[mi] + kOffA);
            ldm4(b0, bAdr1[0] + kOffB);
            ldm4(b1, bAdr1[1] + kOffB);
            #pragma unroll
            for (int mi = 0; mi < 4; mi++) {
                mma16(acc[mi][0], a[mi], b0[0], b0[1]);
                mma16(acc[mi][1], a[mi], b0[2], b0[3]);
                mma16(acc[mi][2], a[mi], b1[0], b1[1]);
                mma16(acc[mi][3], a[mi], b1[2], b1[3]);
            }
        }

        // ---- epilogue 1 (no barrier needed: P16 is a private buffer) ----
        #pragma unroll
        for (int ni = 0; ni < 2; ni++) {
            int c0 = 16 * wn + 8 * ni + 2 * t;
            float sb0 = __ldg(sig_b  + iblk * 64 + c0);
            float sb1 = __ldg(sig_b  + iblk * 64 + c0 + 1);
            float gb0 = __ldg(gate_b + iblk * 64 + c0);
            float gb1 = __ldg(gate_b + iblk * 64 + c0 + 1);
            #pragma unroll
            for (int mi = 0; mi < 4; mi++) {
                int r = 64 * wm + 16 * mi + g;
                float p00 = fmaxf(acc[mi][ni][0] + sb0, 0.f) * sigm(acc[mi][ni + 2][0] + gb0);
                float p01 = fmaxf(acc[mi][ni][1] + sb1, 0.f) * sigm(acc[mi][ni + 2][1] + gb1);
                float p10 = fmaxf(acc[mi][ni][2] + sb0, 0.f) * sigm(acc[mi][ni + 2][2] + gb0);
                float p11 = fmaxf(acc[mi][ni][3] + sb1, 0.f) * sigm(acc[mi][ni + 2][3] + gb1);
                P16u[r * P_STRW + (c0 >> 1)]       = packh2(p00, p01);
                P16u[(r + 8) * P_STRW + (c0 >> 1)] = packh2(p10, p11);
            }
        }
        __syncthreads();   // barrier A: W1 reads done, P16 visible

        // stage next W1 (or W3 on last iter) into freed REG region
        if (iblk + 1 < NBLK) {
            for (int idx = tid; idx < 2176; idx += NTH)
                cp16(smem_s + idx * 16, &wpre1[iblk + 1][0] + idx * 8);
        } else {
            for (int idx = tid; idx < 1088; idx += NTH)
                cp16(smem_s + idx * 16, wpre3 + idx * 8);
        }
        CP_COMMIT();

        // ---- GEMM2: D2[128m][64n], warp tile 32m x 32n ----
        float acc2[2][4][4];
        #pragma unroll
        for (int mi = 0; mi < 2; mi++)
            #pragma unroll
            for (int ni = 0; ni < 4; ni++)
                #pragma unroll
                for (int q = 0; q < 4; q++) acc2[mi][ni][q] = 0.f;

        #pragma unroll
        for (int kt = 0; kt < 4; kt++) {
            uint32_t a0[4], a1[4], b0[4], b1[4];
            ldm4(a0, aAdr2[0] + kt * 32);
            ldm4(a1, aAdr2[1] + kt * 32);
            ldm4(b0, bAdr2[0] + kt * 32);
            ldm4(b1, bAdr2[1] + kt * 32);
            mma16(acc2[0][0], a0, b0[0], b0[1]);
            mma16(acc2[1][0], a1, b0[0], b0[1]);
            mma16(acc2[0][1], a0, b0[2], b0[3]);
            mma16(acc2[1][1], a1, b0[2], b0[3]);
            mma16(acc2[0][2], a0, b1[0], b1[1]);
            mma16(acc2[1][2], a1, b1[0], b1[1]);
            mma16(acc2[0][3], a0, b1[2], b1[3]);
            mma16(acc2[1][3], a1, b1[2], b1[3]);
        }
        __syncthreads();   // barrier B: P16/W2 reads done

        if (iblk + 1 < NBLK) {
            for (int idx = tid; idx < 576; idx += NTH)
                cp16(smem_s + W2_OFFB + idx * 16, &wpre2[iblk + 1][0] + idx * 8);
        }
        CP_COMMIT();

        // ---- epilogue 2: residual update (overlapped with cp.async) ----
        const float* obp = out_b + iblk * 64;
        #pragma unroll
        for (int mi = 0; mi < 2; mi++)
            #pragma unroll
            for (int ni = 0; ni < 4; ni++) {
                int r0 = 32 * wm2 + 16 * mi + g;
                int c0 = 32 * wn2 + 8 * ni + 2 * t;
                float ob0 = __ldg(obp + c0);
                float ob1 = __ldg(obp + c0 + 1);
                float2* gp0 = (float2*)(G + r0 * G32_STRF + c0);        // row r0+1
                float2* gp1 = (float2*)(G + (r0 + 8) * G32_STRF + c0);  // row r0+9
                float2 o0 = *gp0, o1 = *gp1;
                float v00 = acc2[mi][ni][0] + ob0 + o0.x;
                float v01 = acc2[mi][ni][1] + ob1 + o0.y;
                float v10 = acc2[mi][ni][2] + ob0 + o1.x;
                float v11 = acc2[mi][ni][3] + ob1 + o1.y;
                if (tbase + r0 < 0)     { v00 = 0.f; v01 = 0.f; }
                if (tbase + r0 + 8 < 0) { v10 = 0.f; v11 = 0.f; }
                *gp0 = make_float2(v00, v01);
                *gp1 = make_float2(v10, v11);
                G16u[(r0 + 1) * G16_STRW + (c0 >> 1)] = packh2(v00, v01);
                G16u[(r0 + 9) * G16_STRW + (c0 >> 1)] = packh2(v10, v11);
            }
        CP_WAIT0();
        __syncthreads();   // barrier C: G16/G32/weights ready for next iter
    }

    // ================= skip (last timestep, last chunk only) =================
    if (chunk == NCHUNK - 1 && tid < 64) {
        float acc = __ldg(skip_b + tid);   // t=4095 -> row 21 -> (21-1)*66
        #pragma unroll 8
        for (int c = 0; c < 64; c++)
            acc += __ldg(skip_w + tid * 64 + c) * G[20 * G32_STRF + c];
        out[(size_t)BATCH * CCH * TOUT + b * 64 + tid] = acc;
    }
    __syncthreads();   // skip's G32 reads done before GD overlays it

    // ---- GD gather: GD[jl][tap*64+c] = G16[2jl+5+tap][c], 272B rows ----
    for (int idx = tid; idx < 4096; idx += NTH) {
        int jl = idx >> 6, kw = idx & 63;
        int tap = kw >> 5, cw = kw & 31;
        int q = 2 * jl + 5 + tap;
        if (q > 128) q = 128;
        GDu[jl * GD_STRW + kw] = G16u[q * G16_STRW + cw];
    }
    __syncthreads();

    // ================= dilated conv (GEMM3, 64m x 64n x 128k) =================
    const int wm3 = w >> 2;   // 0..1 : 32-row blocks
    const int wn3 = w & 3;    // 0..3 : 16-col blocks
    uint32_t aAdr3[2];
    #pragma unroll
    for (int mi = 0; mi < 2; mi++)
        aAdr3[mi] = smem_s + GD_OFFB
                  + (32 * wm3 + 16 * mi + matLo * 8 + lmrow) * W1_STRB + matHi * 16;
    const uint32_t bAdr3 = smem_s + (16 * wn3 + matHi * 8 + lmrow) * W1_STRB + matLo * 16;

    float acc3[2][2][4];
    #pragma unroll
    for (int mi = 0; mi < 2; mi++)
        #pragma unroll
        for (int ni = 0; ni < 2; ni++)
            #pragma unroll
            for (int q = 0; q < 4; q++) acc3[mi][ni][q] = 0.f;

    #pragma unroll
    for (int kt = 0; kt < 8; kt++) {
        uint32_t a0[4], a1[4], bb[4];
        ldm4(a0, aAdr3[0] + kt * 32);
        ldm4(a1, aAdr3[1] + kt * 32);
        ldm4(bb, bAdr3 + kt * 32);
        mma16(acc3[0][0], a0, bb[0], bb[1]);
        mma16(acc3[1][0], a1, bb[0], bb[1]);
        mma16(acc3[0][1], a0, bb[2], bb[3]);
        mma16(acc3[1][1], a1, bb[2], bb[3]);
    }

    // epilogue 3: transpose through SD (disjoint from W3 region)
    #pragma unroll
    for (int ni = 0; ni < 2; ni++) {
        int cc0 = 16 * wn3 + 8 * ni + 2 * t;
        float db0 = __ldg(dil_b + cc0);
        float db1 = __ldg(dil_b + cc0 + 1);
        #pragma unroll
        for (int mi = 0; mi < 2; mi++) {
            int jl0 = 32 * wm3 + 16 * mi + g;
            if (jl0 < JC) {
                SD[cc0 * SD_STRF + jl0]       = acc3[mi][ni][0] + db0;
                SD[(cc0 + 1) * SD_STRF + jl0] = acc3[mi][ni][1] + db1;
            }
            int jl1 = jl0 + 8;
            if (jl1 < JC) {
                SD[cc0 * SD_STRF + jl1]       = acc3[mi][ni][2] + db0;
                SD[(cc0 + 1) * SD_STRF + jl1] = acc3[mi][ni][3] + db1;
            }
        }
    }
    __syncthreads();

    float* outb = out + (size_t)b * CCH * TOUT;
    #pragma unroll
    for (int cc = 0; cc < 8; cc++) {
        int c = 8 * w + cc;
        for (int jl = l; jl < JC; jl += 32) {
            int j = j0 + jl;
            if (j < TOUT) outb[c * TOUT + j] = SD[c * SD_STRF + jl];
        }
    }
}

extern "C" void kernel_launch(void* const* d_in, const int* in_sizes, int n_in,
                              void* d_out, int out_size)
{
    (void)in_sizes; (void)n_in; (void)out_size;
    const float* x      = (const float*)d_in[0];
    const float* sig_w  = (const float*)d_in[1];
    const float* sig_b  = (const float*)d_in[2];
    const float* gate_w = (const float*)d_in[3];
    const float* gate_b = (const float*)d_in[4];
    const float* out_w  = (const float*)d_in[5];
    const float* out_b  = (const float*)d_in[6];
    const float* skip_w = (const float*)d_in[7];
    const float* skip_b = (const float*)d_in[8];
    const float* dil_w  = (const float*)d_in[9];
    const float* dil_b  = (const float*)d_in[10];
    float* out = (float*)d_out;

    prep_weights<<<96, 256>>>(sig_w, gate_w, out_w, dil_w);

    cudaFuncSetAttribute(wavenet_h16_kernel,
                         cudaFuncAttributeMaxDynamicSharedMemorySize, SMEM_BYTES);
    dim3 grid(NCHUNK, BATCH, 1);
    wavenet_h16_kernel<<<grid, NTH, SMEM_BYTES>>>(
        x, sig_b, gate_b, out_b, skip_w, skip_b, dil_b, out);
}

// round 12
// speedup vs baseline: 1.1839x; 1.1839x over previous
#include <cuda_runtime.h>
#include <cuda_fp16.h>
#include <cstdint>

// Problem constants
#define BATCH 256
#define CCH   64
#define TLEN  4096
#define NBLK  4
#define TOUT  2048
#define JC    60
#define NCHUNK 35
#define NTH   512

// ---- SMEM byte layout (total 114832, 2 CTAs/SM) ----
// W1   [0, 34816):      fp16 [128][272B] (GEMM1) / W3 fp16 [64][272B] (GEMM3)
// W2   [34816, 44032):  fp16 [64][144B]
// P16  [44032, 62464):  fp16 [128][144B] (disjoint -> epi1 needs no pre-barrier)
//                       SD fp32 [64][68f] overlays (epilogue 3 only)
// G32  [62464, 96256):  fp32 rows 1..128, stride 66 floats
//                       GD16 fp16 [64][272B] overlays (dilated A, after skip)
// G16  [96256, 114832): fp16 [129][144B]
#define W1_STRB 272
#define P_STRB  144
#define P_STRW  36
#define W2_OFFB 34816
#define P16_OFFB 44032
#define SD_OFFF 11008
#define SD_STRF 68
#define G32_OFFF 15616
#define G32_STRF 66
#define GD_OFFB 62464
#define GD_STRW 68
#define G16_OFFB 96256
#define G16_OFFH 48128
#define G16_STRB 144
#define G16_STRH 72
#define G16_STRW 36
#define SMEM_BYTES 114832

// Pre-converted fp16 weights in SMEM row layout
__device__ __align__(16) __half wpre1[NBLK][128 * 136];  // sig/gate interleaved
__device__ __align__(16) __half wpre2[NBLK][64 * 72];    // out_w
__device__ __align__(16) __half wpre3[64 * 136];         // dil_w

__global__ void __launch_bounds__(256)
prep_weights(const float* __restrict__ sig_w, const float* __restrict__ gate_w,
             const float* __restrict__ out_w, const float* __restrict__ dil_w)
{
    int tid0 = blockIdx.x * 256 + threadIdx.x;
    int nth  = gridDim.x * 256;
    for (int idx = tid0; idx < NBLK * 128 * 128; idx += nth) {
        int iblk = idx >> 14, r = (idx >> 7) & 127, k = idx & 127;
        int wn = r >> 5, rr = r & 31;
        int h  = 16 * wn + (rr & 15);
        const float* src = (rr < 16 ? sig_w : gate_w) + iblk * 8192;
        wpre1[iblk][r * 136 + k] = __float2half(src[h * 128 + (k & 63) * 2 + (k >> 6)]);
    }
    for (int idx = tid0; idx < NBLK * 64 * 64; idx += nth) {
        int iblk = idx >> 12, c = (idx >> 6) & 63, h = idx & 63;
        wpre2[iblk][c * 72 + h] = __float2half(out_w[iblk * 4096 + c * 64 + h]);
    }
    for (int idx = tid0; idx < 64 * 128; idx += nth) {
        int cc = idx >> 7, k = idx & 127;
        wpre3[cc * 136 + k] = __float2half(dil_w[cc * 128 + (k & 63) * 2 + (k >> 6)]);
    }
}

__device__ __forceinline__ uint32_t packh2(float lo, float hi) {
    __half2 h = __floats2half2_rn(lo, hi);
    return *reinterpret_cast<uint32_t*>(&h);
}
__device__ __forceinline__ float sigm(float v) { return 1.f / (1.f + __expf(-v)); }
__device__ __forceinline__ void mma16(float d[4], const uint32_t a[4],
                                      uint32_t b0, uint32_t b1) {
    asm volatile(
        "mma.sync.aligned.m16n8k16.row.col.f32.f16.f16.f32 "
        "{%0,%1,%2,%3}, {%4,%5,%6,%7}, {%8,%9}, {%0,%1,%2,%3};"
        : "+f"(d[0]), "+f"(d[1]), "+f"(d[2]), "+f"(d[3])
        : "r"(a[0]), "r"(a[1]), "r"(a[2]), "r"(a[3]), "r"(b0), "r"(b1));
}
__device__ __forceinline__ void ldm4(uint32_t r[4], uint32_t addr) {
    asm volatile("ldmatrix.sync.aligned.m8n8.x4.shared.b16 {%0,%1,%2,%3}, [%4];"
        : "=r"(r[0]), "=r"(r[1]), "=r"(r[2]), "=r"(r[3]) : "r"(addr));
}
__device__ __forceinline__ void ldm2(uint32_t& r0, uint32_t& r1, uint32_t addr) {
    asm volatile("ldmatrix.sync.aligned.m8n8.x2.shared.b16 {%0,%1}, [%2];"
        : "=r"(r0), "=r"(r1) : "r"(addr));
}
__device__ __forceinline__ void cp16(uint32_t dst, const __half* src) {
    asm volatile("cp.async.cg.shared.global [%0], [%1], 16;"
        :: "r"(dst), "l"(__cvta_generic_to_global(src)));
}
#define CP_COMMIT() asm volatile("cp.async.commit_group;" ::: "memory")
#define CP_WAIT0()  asm volatile("cp.async.wait_group 0;" ::: "memory")

__global__ void __launch_bounds__(NTH, 2)
wavenet_h16_kernel(const float* __restrict__ x,
                   const float* __restrict__ sig_b, const float* __restrict__ gate_b,
                   const float* __restrict__ out_b,
                   const float* __restrict__ skip_w, const float* __restrict__ skip_b,
                   const float* __restrict__ dil_b,
                   float* __restrict__ out)
{
    extern __shared__ float sm[];
    uint32_t* P16u = (uint32_t*)((char*)sm + P16_OFFB);
    float*    SD   = sm + SD_OFFF;
    float*    G    = sm + G32_OFFF;          // row q at (q-1)*66, q=1..128
    uint32_t* GDu  = (uint32_t*)((char*)sm + GD_OFFB);
    __half*   G16h = (__half*)sm + G16_OFFH;
    uint32_t* G16u = (uint32_t*)((char*)sm + G16_OFFB);

    const uint32_t smem_s = (uint32_t)__cvta_generic_to_shared(sm);

    const int tid = threadIdx.x;
    const int w   = tid >> 5;
    const int l   = tid & 31;
    const int g   = l >> 2;
    const int t   = l & 3;
    const int wm  = w >> 2;        // m-block (rows 32*wm..+32)
    const int wn  = w & 3;         // n-block: channels 16*wn..+16 (sig+gate)
    const int matLo = (l >> 3) & 1;
    const int matHi = l >> 4;
    const int lmrow = l & 7;

    const int b     = blockIdx.y;
    const int chunk = blockIdx.x;
    const int j0    = chunk * JC;
    const int tbase = 2 * j0 - 5;

    // ---- prologue: stage W1(0)+W2(0) via cp.async, overlapped with x-load ----
    for (int idx = tid; idx < 2176; idx += NTH)
        cp16(smem_s + idx * 16, &wpre1[0][0] + idx * 8);
    for (int idx = tid; idx < 576; idx += NTH)
        cp16(smem_s + W2_OFFB + idx * 16, &wpre2[0][0] + idx * 8);
    CP_COMMIT();

    // ---- load x tile into G32 (rows 1..128) and G16 (rows 0..128) ----
    const float* xb = x + (size_t)b * CCH * TLEN;
    for (int c = w; c < CCH; c += 16) {
        const float* xc = xb + c * TLEN;
        for (int q = l; q < 129; q += 32) {
            int tt = tbase + q - 1;
            float v = (tt >= 0 && tt < TLEN) ? xc[tt] : 0.f;
            if (q >= 1) G[(q - 1) * G32_STRF + c] = v;
            G16h[q * G16_STRH + c] = __float2half(v);
        }
    }
    CP_WAIT0();
    __syncthreads();

    // ldmatrix base addresses
    uint32_t aAdr1[2];
    #pragma unroll
    for (int mi = 0; mi < 2; mi++)
        aAdr1[mi] = smem_s + G16_OFFB
                  + (32 * wm + 16 * mi + matLo * 8 + lmrow) * G16_STRB + matHi * 16;
    uint32_t bAdr1[2];
    #pragma unroll
    for (int p = 0; p < 2; p++)
        bAdr1[p] = smem_s + (32 * wn + 16 * p + matHi * 8 + lmrow) * W1_STRB + matLo * 16;
    const uint32_t aAdr2base = smem_s + P16_OFFB
                             + (32 * wm + matLo * 8 + lmrow) * P_STRB + matHi * 16;
    const uint32_t bAdr2 = smem_s + W2_OFFB
                         + (16 * wn + matHi * 8 + lmrow) * P_STRB + matLo * 16;

    // ================= 4 residual blocks (3 barriers each) =================
    for (int iblk = 0; iblk < NBLK; iblk++) {
        // ---- GEMM1: D[128m][128n] ; A[m][tap*64+c] = G16[m+tap][c] ----
        float acc[2][4][4];
        #pragma unroll
        for (int mi = 0; mi < 2; mi++)
            #pragma unroll
            for (int ni = 0; ni < 4; ni++)
                #pragma unroll
                for (int q = 0; q < 4; q++) acc[mi][ni][q] = 0.f;

        #pragma unroll
        for (int kt = 0; kt < 8; kt++) {
            const uint32_t kOffA = (kt >> 2) * G16_STRB + (kt & 3) * 32;
            const uint32_t kOffB = kt * 32;
            uint32_t a0[4], a1[4], bb[4];
            ldm4(a0, aAdr1[0] + kOffA);
            ldm4(a1, aAdr1[1] + kOffA);
            ldm4(bb, bAdr1[0] + kOffB);
            mma16(acc[0][0], a0, bb[0], bb[1]);
            mma16(acc[1][0], a1, bb[0], bb[1]);
            mma16(acc[0][1], a0, bb[2], bb[3]);
            mma16(acc[1][1], a1, bb[2], bb[3]);
            ldm4(bb, bAdr1[1] + kOffB);
            mma16(acc[0][2], a0, bb[0], bb[1]);
            mma16(acc[1][2], a1, bb[0], bb[1]);
            mma16(acc[0][3], a0, bb[2], bb[3]);
            mma16(acc[1][3], a1, bb[2], bb[3]);
        }

        // ---- epilogue 1: warp-local gating straight into disjoint P16 ----
        #pragma unroll
        for (int ni = 0; ni < 2; ni++) {
            int c0 = 16 * wn + 8 * ni + 2 * t;
            float sb0 = __ldg(sig_b  + iblk * 64 + c0);
            float sb1 = __ldg(sig_b  + iblk * 64 + c0 + 1);
            float gb0 = __ldg(gate_b + iblk * 64 + c0);
            float gb1 = __ldg(gate_b + iblk * 64 + c0 + 1);
            #pragma unroll
            for (int mi = 0; mi < 2; mi++) {
                int r = 32 * wm + 16 * mi + g;
                float p00 = fmaxf(acc[mi][ni][0] + sb0, 0.f) * sigm(acc[mi][ni + 2][0] + gb0);
                float p01 = fmaxf(acc[mi][ni][1] + sb1, 0.f) * sigm(acc[mi][ni + 2][1] + gb1);
                float p10 = fmaxf(acc[mi][ni][2] + sb0, 0.f) * sigm(acc[mi][ni + 2][2] + gb0);
                float p11 = fmaxf(acc[mi][ni][3] + sb1, 0.f) * sigm(acc[mi][ni + 2][3] + gb1);
                P16u[r * P_STRW + (c0 >> 1)]       = packh2(p00, p01);
                P16u[(r + 8) * P_STRW + (c0 >> 1)] = packh2(p10, p11);
            }
        }
        __syncthreads();   // barrier A: P16 visible; W1 reads done

        // stage next W1 (or W3) into freed W1 region; overlaps GEMM2+epi2
        if (iblk + 1 < NBLK) {
            for (int idx = tid; idx < 2176; idx += NTH)
                cp16(smem_s + idx * 16, &wpre1[iblk + 1][0] + idx * 8);
        } else {
            for (int idx = tid; idx < 1088; idx += NTH)
                cp16(smem_s + idx * 16, wpre3 + idx * 8);
        }
        CP_COMMIT();

        // ---- GEMM2: D2[128m][64n] = P16 x W2^T ----
        float acc2[2][2][4];
        #pragma unroll
        for (int mi = 0; mi < 2; mi++)
            #pragma unroll
            for (int ni = 0; ni < 2; ni++)
                #pragma unroll
                for (int q = 0; q < 4; q++) acc2[mi][ni][q] = 0.f;

        #pragma unroll
        for (int kt = 0; kt < 4; kt++) {
            uint32_t a0[4], a1[4], bb[4];
            ldm4(a0, aAdr2base + kt * 32);
            ldm4(a1, aAdr2base + 16 * P_STRB + kt * 32);
            ldm4(bb, bAdr2 + kt * 32);
            mma16(acc2[0][0], a0, bb[0], bb[1]);
            mma16(acc2[1][0], a1, bb[0], bb[1]);
            mma16(acc2[0][1], a0, bb[2], bb[3]);
            mma16(acc2[1][1], a1, bb[2], bb[3]);
        }
        __syncthreads();   // barrier B: W2/P16 reads done

        if (iblk + 1 < NBLK) {
            for (int idx = tid; idx < 576; idx += NTH)
                cp16(smem_s + W2_OFFB + idx * 16, &wpre2[iblk + 1][0] + idx * 8);
        }
        CP_COMMIT();

        // ---- epilogue 2: residual update (overlapped with cp.async) ----
        const float* obp = out_b + iblk * 64;
        #pragma unroll
        for (int mi = 0; mi < 2; mi++)
            #pragma unroll
            for (int ni = 0; ni < 2; ni++) {
                int r0 = 32 * wm + 16 * mi + g;
                int c0 = 16 * wn + 8 * ni + 2 * t;
                float ob0 = __ldg(obp + c0);
                float ob1 = __ldg(obp + c0 + 1);
                float2* gp0 = (float2*)(G + r0 * G32_STRF + c0);        // row r0+1
                float2* gp1 = (float2*)(G + (r0 + 8) * G32_STRF + c0);  // row r0+9
                float2 o0 = *gp0, o1 = *gp1;
                float v00 = acc2[mi][ni][0] + ob0 + o0.x;
                float v01 = acc2[mi][ni][1] + ob1 + o0.y;
                float v10 = acc2[mi][ni][2] + ob0 + o1.x;
                float v11 = acc2[mi][ni][3] + ob1 + o1.y;
                if (tbase + r0 < 0)     { v00 = 0.f; v01 = 0.f; }
                if (tbase + r0 + 8 < 0) { v10 = 0.f; v11 = 0.f; }
                *gp0 = make_float2(v00, v01);
                *gp1 = make_float2(v10, v11);
                G16u[(r0 + 1) * G16_STRW + (c0 >> 1)] = packh2(v00, v01);
                G16u[(r0 + 9) * G16_STRW + (c0 >> 1)] = packh2(v10, v11);
            }
        CP_WAIT0();
        __syncthreads();   // barrier C: G16/G32/weights ready
    }

    // ================= skip (last timestep, last chunk only) =================
    if (chunk == NCHUNK - 1 && tid < 64) {
        float acc = __ldg(skip_b + tid);   // t=4095 -> row 21 -> (21-1)*66
        #pragma unroll 8
        for (int c = 0; c < 64; c++)
            acc += __ldg(skip_w + tid * 64 + c) * G[20 * G32_STRF + c];
        out[(size_t)BATCH * CCH * TOUT + b * 64 + tid] = acc;
    }
    __syncthreads();   // skip's G32 reads done before GD overlays it

    // ---- GD gather: GD[jl][tap*64+c] = G16[2jl+5+tap][c], 272B rows ----
    for (int idx = tid; idx < 4096; idx += NTH) {
        int jl = idx >> 6, kw = idx & 63;
        int tap = kw >> 5, cw = kw & 31;
        int q = 2 * jl + 5 + tap;
        if (q > 128) q = 128;
        GDu[jl * GD_STRW + kw] = G16u[q * G16_STRW + cw];
    }
    __syncthreads();

    // ================= dilated stride-2 conv (GEMM3, M=64) =================
    const int wm3 = w >> 3;
    const int wn3 = w & 7;
    const uint32_t bAdr3 = smem_s + (8 * wn3 + lmrow) * W1_STRB + matLo * 16;
    uint32_t aAdr3[2];
    #pragma unroll
    for (int mi = 0; mi < 2; mi++)
        aAdr3[mi] = smem_s + GD_OFFB
                  + (32 * wm3 + 16 * mi + matLo * 8 + lmrow) * W1_STRB + matHi * 16;

    float acc3[2][4];
    #pragma unroll
    for (int mi = 0; mi < 2; mi++)
        #pragma unroll
        for (int q = 0; q < 4; q++) acc3[mi][q] = 0.f;

    #pragma unroll
    for (int kt = 0; kt < 8; kt++) {
        uint32_t a0[4], a1[4], b0, b1;
        ldm4(a0, aAdr3[0] + kt * 32);
        ldm4(a1, aAdr3[1] + kt * 32);
        ldm2(b0, b1, bAdr3 + kt * 32);
        mma16(acc3[0], a0, b0, b1);
        mma16(acc3[1], a1, b0, b1);
    }
    __syncthreads();   // P16 dead -> SD overlay safe

    // epilogue 3: transpose through SD, then coalesced stores
    {
        int cc0 = 8 * wn3 + 2 * t;
        float db0 = __ldg(dil_b + cc0);
        float db1 = __ldg(dil_b + cc0 + 1);
        #pragma unroll
        for (int mi = 0; mi < 2; mi++) {
            int jl0 = 32 * wm3 + 16 * mi + g;
            if (jl0 < JC) {
                SD[cc0 * SD_STRF + jl0]       = acc3[mi][0] + db0;
                SD[(cc0 + 1) * SD_STRF + jl0] = acc3[mi][1] + db1;
            }
            int jl1 = jl0 + 8;
            if (jl1 < JC) {
                SD[cc0 * SD_STRF + jl1]       = acc3[mi][2] + db0;
                SD[(cc0 + 1) * SD_STRF + jl1] = acc3[mi][3] + db1;
            }
        }
    }
    __syncthreads();

    float* outb = out + (size_t)b * CCH * TOUT;
    #pragma unroll
    for (int cc = 0; cc < 4; cc++) {
        int c = 4 * w + cc;
        for (int jl = l; jl < JC; jl += 32) {
            int j = j0 + jl;
            if (j < TOUT) outb[c * TOUT + j] = SD[c * SD_STRF + jl];
        }
    }
}

extern "C" void kernel_launch(void* const* d_in, const int* in_sizes, int n_in,
                              void* d_out, int out_size)
{
    (void)in_sizes; (void)n_in; (void)out_size;
    const float* x      = (const float*)d_in[0];
    const float* sig_w  = (const float*)d_in[1];
    const float* sig_b  = (const float*)d_in[2];
    const float* gate_w = (const float*)d_in[3];
    const float* gate_b = (const float*)d_in[4];
    const float* out_w  = (const float*)d_in[5];
    const float* out_b  = (const float*)d_in[6];
    const float* skip_w = (const float*)d_in[7];
    const float* skip_b = (const float*)d_in[8];
    const float* dil_w  = (const float*)d_in[9];
    const float* dil_b  = (const float*)d_in[10];
    float* out = (float*)d_out;

    prep_weights<<<96, 256>>>(sig_w, gate_w, out_w, dil_w);

    cudaFuncSetAttribute(wavenet_h16_kernel,
                         cudaFuncAttributeMaxDynamicSharedMemorySize, SMEM_BYTES);
    dim3 grid(NCHUNK, BATCH, 1);
    wavenet_h16_kernel<<<grid, NTH, SMEM_BYTES>>>(
        x, sig_b, gate_b, out_b, skip_w, skip_b, dil_b, out);
}

// round 13
// speedup vs baseline: 1.2078x; 1.0202x over previous
#include <cuda_runtime.h>
#include <cuda_fp16.h>
#include <cstdint>

// Problem constants
#define BATCH 256
#define CCH   64
#define TLEN  4096
#define NBLK  4
#define TOUT  2048
#define JC    62
#define NCHUNK 34        // ceil(2048/62)
#define NTH   512

// ---- SMEM byte layout (total 114832, 2 CTAs/SM) ----
// W1   [0, 34816):      fp16 [128][272B] (GEMM1) / W3 fp16 [64][272B] (GEMM3)
// W2   [34816, 44032):  fp16 [64][144B]
// P16  [44032, 62464):  fp16 [128][144B] (disjoint); SD fp32 [64][68f] overlays
// G32  [62464, 96256):  fp32 rows 1..128, stride 66 floats
//                       GD16 fp16 [64][272B] overlays (dilated A, after skip)
// G16  [96256, 114832): fp16 [129][144B]
#define W1_STRB 272
#define P_STRB  144
#define P_STRW  36
#define W2_OFFB 34816
#define P16_OFFB 44032
#define SD_OFFF 11008
#define SD_STRF 68
#define G32_OFFF 15616
#define G32_STRF 66
#define GD_OFFB 62464
#define GD_STRW 68
#define G16_OFFB 96256
#define G16_OFFH 48128
#define G16_STRB 144
#define G16_STRH 72
#define G16_STRW 36
#define SMEM_BYTES 114832

// Pre-converted fp16 weights in SMEM row layout
__device__ __align__(16) __half wpre1[NBLK][128 * 136];  // sig/gate interleaved
__device__ __align__(16) __half wpre2[NBLK][64 * 72];    // out_w
__device__ __align__(16) __half wpre3[64 * 136];         // dil_w

__global__ void __launch_bounds__(256)
prep_weights(const float* __restrict__ sig_w, const float* __restrict__ gate_w,
             const float* __restrict__ out_w, const float* __restrict__ dil_w)
{
    int tid0 = blockIdx.x * 256 + threadIdx.x;
    int nth  = gridDim.x * 256;
    for (int idx = tid0; idx < NBLK * 128 * 128; idx += nth) {
        int iblk = idx >> 14, r = (idx >> 7) & 127, k = idx & 127;
        int wn = r >> 5, rr = r & 31;
        int h  = 16 * wn + (rr & 15);
        const float* src = (rr < 16 ? sig_w : gate_w) + iblk * 8192;
        wpre1[iblk][r * 136 + k] = __float2half(src[h * 128 + (k & 63) * 2 + (k >> 6)]);
    }
    for (int idx = tid0; idx < NBLK * 64 * 64; idx += nth) {
        int iblk = idx >> 12, c = (idx >> 6) & 63, h = idx & 63;
        wpre2[iblk][c * 72 + h] = __float2half(out_w[iblk * 4096 + c * 64 + h]);
    }
    for (int idx = tid0; idx < 64 * 128; idx += nth) {
        int cc = idx >> 7, k = idx & 127;
        wpre3[cc * 136 + k] = __float2half(dil_w[cc * 128 + (k & 63) * 2 + (k >> 6)]);
    }
}

__device__ __forceinline__ uint32_t packh2(float lo, float hi) {
    __half2 h = __floats2half2_rn(lo, hi);
    return *reinterpret_cast<uint32_t*>(&h);
}
__device__ __forceinline__ float sigm(float v) { return 1.f / (1.f + __expf(-v)); }
__device__ __forceinline__ void mma16(float d[4], const uint32_t a[4],
                                      uint32_t b0, uint32_t b1) {
    asm volatile(
        "mma.sync.aligned.m16n8k16.row.col.f32.f16.f16.f32 "
        "{%0,%1,%2,%3}, {%4,%5,%6,%7}, {%8,%9}, {%0,%1,%2,%3};"
        : "+f"(d[0]), "+f"(d[1]), "+f"(d[2]), "+f"(d[3])
        : "r"(a[0]), "r"(a[1]), "r"(a[2]), "r"(a[3]), "r"(b0), "r"(b1));
}
__device__ __forceinline__ void ldm4(uint32_t r[4], uint32_t addr) {
    asm volatile("ldmatrix.sync.aligned.m8n8.x4.shared.b16 {%0,%1,%2,%3}, [%4];"
        : "=r"(r[0]), "=r"(r[1]), "=r"(r[2]), "=r"(r[3]) : "r"(addr));
}
__device__ __forceinline__ void ldm2(uint32_t& r0, uint32_t& r1, uint32_t addr) {
    asm volatile("ldmatrix.sync.aligned.m8n8.x2.shared.b16 {%0,%1}, [%2];"
        : "=r"(r0), "=r"(r1) : "r"(addr));
}
__device__ __forceinline__ void cp16(uint32_t dst, const __half* src) {
    asm volatile("cp.async.cg.shared.global [%0], [%1], 16;"
        :: "r"(dst), "l"(__cvta_generic_to_global(src)));
}
#define CP_COMMIT() asm volatile("cp.async.commit_group;" ::: "memory")
#define CP_WAIT0()  asm volatile("cp.async.wait_group 0;" ::: "memory")

__global__ void __launch_bounds__(NTH, 2)
wavenet_h16_kernel(const float* __restrict__ x,
                   const float* __restrict__ sig_b, const float* __restrict__ gate_b,
                   const float* __restrict__ out_b,
                   const float* __restrict__ skip_w, const float* __restrict__ skip_b,
                   const float* __restrict__ dil_b,
                   float* __restrict__ out)
{
    extern __shared__ float sm[];
    uint32_t* P16u = (uint32_t*)((char*)sm + P16_OFFB);
    float*    SD   = sm + SD_OFFF;
    float*    G    = sm + G32_OFFF;          // row q at (q-1)*66, q=1..128
    uint32_t* GDu  = (uint32_t*)((char*)sm + GD_OFFB);
    __half*   G16h = (__half*)sm + G16_OFFH;
    uint32_t* G16u = (uint32_t*)((char*)sm + G16_OFFB);

    const uint32_t smem_s = (uint32_t)__cvta_generic_to_shared(sm);

    const int tid = threadIdx.x;
    const int w   = tid >> 5;
    const int l   = tid & 31;
    const int g   = l >> 2;
    const int t   = l & 3;
    const int wm  = w >> 2;        // m-block (rows 32*wm..+32)
    const int wn  = w & 3;         // n-block: channels 16*wn..+16 (sig+gate)
    const int matLo = (l >> 3) & 1;
    const int matHi = l >> 4;
    const int lmrow = l & 7;

    const int b     = blockIdx.y;
    const int chunk = blockIdx.x;
    const int j0    = chunk * JC;
    const int tbase = 2 * j0 - 5;

    // ---- prologue: stage W1(0)+W2(0) via cp.async, overlapped with x-load ----
    for (int idx = tid; idx < 2176; idx += NTH)
        cp16(smem_s + idx * 16, &wpre1[0][0] + idx * 8);
    for (int idx = tid; idx < 576; idx += NTH)
        cp16(smem_s + W2_OFFB + idx * 16, &wpre2[0][0] + idx * 8);
    CP_COMMIT();

    // ---- load x tile into G32 (rows 1..128) and G16 (rows 0..128) ----
    const float* xb = x + (size_t)b * CCH * TLEN;
    for (int c = w; c < CCH; c += 16) {
        const float* xc = xb + c * TLEN;
        for (int q = l; q < 129; q += 32) {
            int tt = tbase + q - 1;
            float v = (tt >= 0 && tt < TLEN) ? xc[tt] : 0.f;
            if (q >= 1) G[(q - 1) * G32_STRF + c] = v;
            G16h[q * G16_STRH + c] = __float2half(v);
        }
    }
    CP_WAIT0();
    __syncthreads();

    // ldmatrix base addresses
    uint32_t aAdr1[2];
    #pragma unroll
    for (int mi = 0; mi < 2; mi++)
        aAdr1[mi] = smem_s + G16_OFFB
                  + (32 * wm + 16 * mi + matLo * 8 + lmrow) * G16_STRB + matHi * 16;
    uint32_t bAdr1[2];
    #pragma unroll
    for (int p = 0; p < 2; p++)
        bAdr1[p] = smem_s + (32 * wn + 16 * p + matHi * 8 + lmrow) * W1_STRB + matLo * 16;
    const uint32_t aAdr2base = smem_s + P16_OFFB
                             + (32 * wm + matLo * 8 + lmrow) * P_STRB + matHi * 16;
    const uint32_t bAdr2 = smem_s + W2_OFFB
                         + (16 * wn + matHi * 8 + lmrow) * P_STRB + matLo * 16;

    // ================= 4 residual blocks (3 barriers each) =================
    for (int iblk = 0; iblk < NBLK; iblk++) {
        // ---- GEMM1: D[128m][128n] ; A[m][tap*64+c] = G16[m+tap][c] ----
        float acc[2][4][4];
        #pragma unroll
        for (int mi = 0; mi < 2; mi++)
            #pragma unroll
            for (int ni = 0; ni < 4; ni++)
                #pragma unroll
                for (int q = 0; q < 4; q++) acc[mi][ni][q] = 0.f;

        #pragma unroll
        for (int kt = 0; kt < 8; kt++) {
            const uint32_t kOffA = (kt >> 2) * G16_STRB + (kt & 3) * 32;
            const uint32_t kOffB = kt * 32;
            uint32_t a0[4], a1[4], bb[4];
            ldm4(a0, aAdr1[0] + kOffA);
            ldm4(a1, aAdr1[1] + kOffA);
            ldm4(bb, bAdr1[0] + kOffB);
            mma16(acc[0][0], a0, bb[0], bb[1]);
            mma16(acc[1][0], a1, bb[0], bb[1]);
            mma16(acc[0][1], a0, bb[2], bb[3]);
            mma16(acc[1][1], a1, bb[2], bb[3]);
            ldm4(bb, bAdr1[1] + kOffB);
            mma16(acc[0][2], a0, bb[0], bb[1]);
            mma16(acc[1][2], a1, bb[0], bb[1]);
            mma16(acc[0][3], a0, bb[2], bb[3]);
            mma16(acc[1][3], a1, bb[2], bb[3]);
        }

        // ---- epilogue 1: warp-local gating straight into disjoint P16 ----
        #pragma unroll
        for (int ni = 0; ni < 2; ni++) {
            int c0 = 16 * wn + 8 * ni + 2 * t;
            float sb0 = __ldg(sig_b  + iblk * 64 + c0);
            float sb1 = __ldg(sig_b  + iblk * 64 + c0 + 1);
            float gb0 = __ldg(gate_b + iblk * 64 + c0);
            float gb1 = __ldg(gate_b + iblk * 64 + c0 + 1);
            #pragma unroll
            for (int mi = 0; mi < 2; mi++) {
                int r = 32 * wm + 16 * mi + g;
                float p00 = fmaxf(acc[mi][ni][0] + sb0, 0.f) * sigm(acc[mi][ni + 2][0] + gb0);
                float p01 = fmaxf(acc[mi][ni][1] + sb1, 0.f) * sigm(acc[mi][ni + 2][1] + gb1);
                float p10 = fmaxf(acc[mi][ni][2] + sb0, 0.f) * sigm(acc[mi][ni + 2][2] + gb0);
                float p11 = fmaxf(acc[mi][ni][3] + sb1, 0.f) * sigm(acc[mi][ni + 2][3] + gb1);
                P16u[r * P_STRW + (c0 >> 1)]       = packh2(p00, p01);
                P16u[(r + 8) * P_STRW + (c0 >> 1)] = packh2(p10, p11);
            }
        }
        __syncthreads();   // barrier A: P16 visible; W1 reads done

        // ---- GEMM2: D2[128m][64n] = P16 x W2^T ----
        float acc2[2][2][4];
        #pragma unroll
        for (int mi = 0; mi < 2; mi++)
            #pragma unroll
            for (int ni = 0; ni < 2; ni++)
                #pragma unroll
                for (int q = 0; q < 4; q++) acc2[mi][ni][q] = 0.f;

        #pragma unroll
        for (int kt = 0; kt < 4; kt++) {
            uint32_t a0[4], a1[4], bb[4];
            ldm4(a0, aAdr2base + kt * 32);
            ldm4(a1, aAdr2base + 16 * P_STRB + kt * 32);
            ldm4(bb, bAdr2 + kt * 32);
            mma16(acc2[0][0], a0, bb[0], bb[1]);
            mma16(acc2[1][0], a1, bb[0], bb[1]);
            mma16(acc2[0][1], a0, bb[2], bb[3]);
            mma16(acc2[1][1], a1, bb[2], bb[3]);
        }
        __syncthreads();   // barrier B: W1/W2/P16 reads all done

        // stage next weights; overlaps ONLY epilogue 2 (keep off the GEMMs)
        if (iblk + 1 < NBLK) {
            for (int idx = tid; idx < 2176; idx += NTH)
                cp16(smem_s + idx * 16, &wpre1[iblk + 1][0] + idx * 8);
            for (int idx = tid; idx < 576; idx += NTH)
                cp16(smem_s + W2_OFFB + idx * 16, &wpre2[iblk + 1][0] + idx * 8);
        } else {
            for (int idx = tid; idx < 1088; idx += NTH)
                cp16(smem_s + idx * 16, wpre3 + idx * 8);
        }
        CP_COMMIT();

        // ---- epilogue 2: residual update (overlapped with cp.async) ----
        const float* obp = out_b + iblk * 64;
        #pragma unroll
        for (int mi = 0; mi < 2; mi++)
            #pragma unroll
            for (int ni = 0; ni < 2; ni++) {
                int r0 = 32 * wm + 16 * mi + g;
                int c0 = 16 * wn + 8 * ni + 2 * t;
                float ob0 = __ldg(obp + c0);
                float ob1 = __ldg(obp + c0 + 1);
                float2* gp0 = (float2*)(G + r0 * G32_STRF + c0);        // row r0+1
                float2* gp1 = (float2*)(G + (r0 + 8) * G32_STRF + c0);  // row r0+9
                float2 o0 = *gp0, o1 = *gp1;
                float v00 = acc2[mi][ni][0] + ob0 + o0.x;
                float v01 = acc2[mi][ni][1] + ob1 + o0.y;
                float v10 = acc2[mi][ni][2] + ob0 + o1.x;
                float v11 = acc2[mi][ni][3] + ob1 + o1.y;
                if (tbase + r0 < 0)     { v00 = 0.f; v01 = 0.f; }
                if (tbase + r0 + 8 < 0) { v10 = 0.f; v11 = 0.f; }
                *gp0 = make_float2(v00, v01);
                *gp1 = make_float2(v10, v11);
                G16u[(r0 + 1) * G16_STRW + (c0 >> 1)] = packh2(v00, v01);
                G16u[(r0 + 9) * G16_STRW + (c0 >> 1)] = packh2(v10, v11);
            }
        CP_WAIT0();
        __syncthreads();   // barrier C: G16/G32/weights ready
    }

    // ================= skip (last timestep, last chunk only) =================
    if (chunk == NCHUNK - 1 && tid < 64) {
        int qs = (TLEN - 1) - tbase + 1;   // G row holding t=4095
        float acc = __ldg(skip_b + tid);
        #pragma unroll 8
        for (int c = 0; c < 64; c++)
            acc += __ldg(skip_w + tid * 64 + c) * G[(qs - 1) * G32_STRF + c];
        out[(size_t)BATCH * CCH * TOUT + b * 64 + tid] = acc;
    }
    __syncthreads();   // skip's G32 reads done before GD overlays it

    // ---- GD gather: GD[jl][tap*64+c] = G16[2jl+5+tap][c], 272B rows ----
    for (int idx = tid; idx < 4096; idx += NTH) {
        int jl = idx >> 6, kw = idx & 63;
        int tap = kw >> 5, cw = kw & 31;
        int q = 2 * jl + 5 + tap;
        if (q > 128) q = 128;
        GDu[jl * GD_STRW + kw] = G16u[q * G16_STRW + cw];
    }
    __syncthreads();

    // ================= dilated stride-2 conv (GEMM3, M=64) =================
    const int wm3 = w >> 3;
    const int wn3 = w & 7;
    const uint32_t bAdr3 = smem_s + (8 * wn3 + lmrow) * W1_STRB + matLo * 16;
    uint32_t aAdr3[2];
    #pragma unroll
    for (int mi = 0; mi < 2; mi++)
        aAdr3[mi] = smem_s + GD_OFFB
                  + (32 * wm3 + 16 * mi + matLo * 8 + lmrow) * W1_STRB + matHi * 16;

    float acc3[2][4];
    #pragma unroll
    for (int mi = 0; mi < 2; mi++)
        #pragma unroll
        for (int q = 0; q < 4; q++) acc3[mi][q] = 0.f;

    #pragma unroll
    for (int kt = 0; kt < 8; kt++) {
        uint32_t a0[4], a1[4], b0, b1;
        ldm4(a0, aAdr3[0] + kt * 32);
        ldm4(a1, aAdr3[1] + kt * 32);
        ldm2(b0, b1, bAdr3 + kt * 32);
        mma16(acc3[0], a0, b0, b1);
        mma16(acc3[1], a1, b0, b1);
    }
    __syncthreads();   // P16 dead -> SD overlay safe

    // epilogue 3: transpose through SD, then coalesced stores
    {
        int cc0 = 8 * wn3 + 2 * t;
        float db0 = __ldg(dil_b + cc0);
        float db1 = __ldg(dil_b + cc0 + 1);
        #pragma unroll
        for (int mi = 0; mi < 2; mi++) {
            int jl0 = 32 * wm3 + 16 * mi + g;
            if (jl0 < JC) {
                SD[cc0 * SD_STRF + jl0]       = acc3[mi][0] + db0;
                SD[(cc0 + 1) * SD_STRF + jl0] = acc3[mi][1] + db1;
            }
            int jl1 = jl0 + 8;
            if (jl1 < JC) {
                SD[cc0 * SD_STRF + jl1]       = acc3[mi][2] + db0;
                SD[(cc0 + 1) * SD_STRF + jl1] = acc3[mi][3] + db1;
            }
        }
    }
    __syncthreads();

    float* outb = out + (size_t)b * CCH * TOUT;
    #pragma unroll
    for (int cc = 0; cc < 4; cc++) {
        int c = 4 * w + cc;
        for (int jl = l; jl < JC; jl += 32) {
            int j = j0 + jl;
            if (j < TOUT) outb[c * TOUT + j] = SD[c * SD_STRF + jl];
        }
    }
}

extern "C" void kernel_launch(void* const* d_in, const int* in_sizes, int n_in,
                              void* d_out, int out_size)
{
    (void)in_sizes; (void)n_in; (void)out_size;
    const float* x      = (const float*)d_in[0];
    const float* sig_w  = (const float*)d_in[1];
    const float* sig_b  = (const float*)d_in[2];
    const float* gate_w = (const float*)d_in[3];
    const float* gate_b = (const float*)d_in[4];
    const float* out_w  = (const float*)d_in[5];
    const float* out_b  = (const float*)d_in[6];
    const float* skip_w = (const float*)d_in[7];
    const float* skip_b = (const float*)d_in[8];
    const float* dil_w  = (const float*)d_in[9];
    const float* dil_b  = (const float*)d_in[10];
    float* out = (float*)d_out;

    prep_weights<<<96, 256>>>(sig_w, gate_w, out_w, dil_w);

    cudaFuncSetAttribute(wavenet_h16_kernel,
                         cudaFuncAttributeMaxDynamicSharedMemorySize, SMEM_BYTES);
    dim3 grid(NCHUNK, BATCH, 1);
    wavenet_h16_kernel<<<grid, NTH, SMEM_BYTES>>>(
        x, sig_b, gate_b, out_b, skip_w, skip_b, dil_b, out);
}

// round 14
// speedup vs baseline: 1.3474x; 1.1156x over previous
#include <cuda_runtime.h>
#include <cuda_fp16.h>
#include <cstdint>

// Problem constants
#define BATCH 256
#define CCH   64
#define TLEN  4096
#define NBLK  4
#define TOUT  2048
#define JC    62
#define NCHUNK 34        // ceil(2048/62)
#define NTH   512

// ---- SMEM byte layout (97696 B -> 2 CTAs/SM, ~38KB L1D carveout) ----
// REG [0, 34816): W1 fp16 [128][272B] (GEMM1) / W3 fp16 [64][272B] (GEMM3)
//   + SD fp32 [64][68f] at byte 17408 (epilogue 3). P16 fp16 [128][144B]
//   overlays REG at byte 0 after GEMM1.
// W2 fp16 [64][144B] at byte 34816
// G32 fp32 [129][68f] at byte 44032; GD16 fp16 [64][272B] overlays (dilated)
// G16 fp16 [129][144B] at byte 79120
#define W1_STRB 272
#define P_STRB  144
#define P_STRW  36
#define W2_OFFB 34816
#define SD_OFFF 4352
#define SD_STRF 68
#define G32_OFFF 11008
#define G_STRF  68
#define GD_OFFB 44032
#define GD_STRW 68
#define G16_OFFB 79120
#define G16_OFFH 39560
#define G16_STRB 144
#define G16_STRH 72
#define SMEM_BYTES 97696

// Pre-converted fp16 weights in SMEM row layout
__device__ __align__(16) __half wpre1[NBLK][128 * 136];  // sig/gate interleaved
__device__ __align__(16) __half wpre2[NBLK][64 * 72];    // out_w
__device__ __align__(16) __half wpre3[64 * 136];         // dil_w

__global__ void __launch_bounds__(256)
prep_weights(const float* __restrict__ sig_w, const float* __restrict__ gate_w,
             const float* __restrict__ out_w, const float* __restrict__ dil_w)
{
    int tid0 = blockIdx.x * 256 + threadIdx.x;
    int nth  = gridDim.x * 256;
    for (int idx = tid0; idx < NBLK * 128 * 128; idx += nth) {
        int iblk = idx >> 14, r = (idx >> 7) & 127, k = idx & 127;
        int wn = r >> 5, rr = r & 31;
        int h  = 16 * wn + (rr & 15);
        const float* src = (rr < 16 ? sig_w : gate_w) + iblk * 8192;
        wpre1[iblk][r * 136 + k] = __float2half(src[h * 128 + (k & 63) * 2 + (k >> 6)]);
    }
    for (int idx = tid0; idx < NBLK * 64 * 64; idx += nth) {
        int iblk = idx >> 12, c = (idx >> 6) & 63, h = idx & 63;
        wpre2[iblk][c * 72 + h] = __float2half(out_w[iblk * 4096 + c * 64 + h]);
    }
    for (int idx = tid0; idx < 64 * 128; idx += nth) {
        int cc = idx >> 7, k = idx & 127;
        wpre3[cc * 136 + k] = __float2half(dil_w[cc * 128 + (k & 63) * 2 + (k >> 6)]);
    }
}

__device__ __forceinline__ uint32_t packh2(float lo, float hi) {
    __half2 h = __floats2half2_rn(lo, hi);
    return *reinterpret_cast<uint32_t*>(&h);
}
__device__ __forceinline__ float sigm(float v) { return 1.f / (1.f + __expf(-v)); }
__device__ __forceinline__ void mma16(float d[4], const uint32_t a[4],
                                      uint32_t b0, uint32_t b1) {
    asm volatile(
        "mma.sync.aligned.m16n8k16.row.col.f32.f16.f16.f32 "
        "{%0,%1,%2,%3}, {%4,%5,%6,%7}, {%8,%9}, {%0,%1,%2,%3};"
        : "+f"(d[0]), "+f"(d[1]), "+f"(d[2]), "+f"(d[3])
        : "r"(a[0]), "r"(a[1]), "r"(a[2]), "r"(a[3]), "r"(b0), "r"(b1));
}
__device__ __forceinline__ void ldm4(uint32_t r[4], uint32_t addr) {
    asm volatile("ldmatrix.sync.aligned.m8n8.x4.shared.b16 {%0,%1,%2,%3}, [%4];"
        : "=r"(r[0]), "=r"(r[1]), "=r"(r[2]), "=r"(r[3]) : "r"(addr));
}
__device__ __forceinline__ void ldm2(uint32_t& r0, uint32_t& r1, uint32_t addr) {
    asm volatile("ldmatrix.sync.aligned.m8n8.x2.shared.b16 {%0,%1}, [%2];"
        : "=r"(r0), "=r"(r1) : "r"(addr));
}
__device__ __forceinline__ void cp16(uint32_t dst, const __half* src) {
    asm volatile("cp.async.cg.shared.global [%0], [%1], 16;"
        :: "r"(dst), "l"(__cvta_generic_to_global(src)));
}
#define CP_COMMIT() asm volatile("cp.async.commit_group;" ::: "memory")
#define CP_WAIT0()  asm volatile("cp.async.wait_group 0;" ::: "memory")

__global__ void __launch_bounds__(NTH, 2)
wavenet_h16_kernel(const float* __restrict__ x,
                   const float* __restrict__ sig_b, const float* __restrict__ gate_b,
                   const float* __restrict__ out_b,
                   const float* __restrict__ skip_w, const float* __restrict__ skip_b,
                   const float* __restrict__ dil_b,
                   float* __restrict__ out)
{
    extern __shared__ float sm[];
    uint32_t* P16u = (uint32_t*)sm;           // overlays W1 after GEMM1
    float*    SD   = sm + SD_OFFF;
    float*    G    = sm + G32_OFFF;
    uint32_t* GDu  = (uint32_t*)((char*)sm + GD_OFFB);
    __half*   G16h = (__half*)sm + G16_OFFH;
    uint32_t* G16u = (uint32_t*)((char*)sm + G16_OFFB);

    const uint32_t smem_s = (uint32_t)__cvta_generic_to_shared(sm);

    const int tid = threadIdx.x;
    const int w   = tid >> 5;
    const int l   = tid & 31;
    const int g   = l >> 2;
    const int t   = l & 3;
    const int wm  = w >> 2;        // m-block (rows 32*wm..+32)
    const int wn  = w & 3;         // n-block: channels 16*wn..+16 (sig+gate)
    const int matLo = (l >> 3) & 1;
    const int matHi = l >> 4;
    const int lmrow = l & 7;

    const int b     = blockIdx.y;
    const int chunk = blockIdx.x;
    const int j0    = chunk * JC;
    const int tbase = 2 * j0 - 5;

    // ---- prologue: stage W1(0)+W2(0) via cp.async, overlapped with x-load ----
    for (int idx = tid; idx < 2176; idx += NTH)
        cp16(smem_s + idx * 16, &wpre1[0][0] + idx * 8);
    for (int idx = tid; idx < 576; idx += NTH)
        cp16(smem_s + W2_OFFB + idx * 16, &wpre2[0][0] + idx * 8);
    CP_COMMIT();

    // ---- load x tile into G32 and G16 ----
    const float* xb = x + (size_t)b * CCH * TLEN;
    for (int c = w; c < CCH; c += 16) {
        const float* xc = xb + c * TLEN;
        for (int q = l; q < 129; q += 32) {
            int tt = tbase + q - 1;
            float v = (tt >= 0 && tt < TLEN) ? xc[tt] : 0.f;
            G[q * G_STRF + c] = v;
            G16h[q * G16_STRH + c] = __float2half(v);
        }
    }
    CP_WAIT0();
    __syncthreads();

    // ldmatrix base addresses
    uint32_t aAdr1[2];
    #pragma unroll
    for (int mi = 0; mi < 2; mi++)
        aAdr1[mi] = smem_s + G16_OFFB
                  + (32 * wm + 16 * mi + matLo * 8 + lmrow) * G16_STRB + matHi * 16;
    uint32_t bAdr1[2];
    #pragma unroll
    for (int p = 0; p < 2; p++)
        bAdr1[p] = smem_s + (32 * wn + 16 * p + matHi * 8 + lmrow) * W1_STRB + matLo * 16;
    const uint32_t aAdr2base = smem_s + (32 * wm + matLo * 8 + lmrow) * P_STRB + matHi * 16;
    const uint32_t bAdr2 = smem_s + W2_OFFB
                         + (16 * wn + matHi * 8 + lmrow) * P_STRB + matLo * 16;

    // ================= 4 residual blocks =================
    for (int iblk = 0; iblk < NBLK; iblk++) {
        // ---- GEMM1: D[128m][128n] ; A[m][tap*64+c] = G16[m+tap][c] ----
        float acc[2][4][4];
        #pragma unroll
        for (int mi = 0; mi < 2; mi++)
            #pragma unroll
            for (int ni = 0; ni < 4; ni++)
                #pragma unroll
                for (int q = 0; q < 4; q++) acc[mi][ni][q] = 0.f;

        #pragma unroll
        for (int kt = 0; kt < 8; kt++) {
            const uint32_t kOffA = (kt >> 2) * G16_STRB + (kt & 3) * 32;
            const uint32_t kOffB = kt * 32;
            uint32_t a0[4], a1[4], bb[4];
            ldm4(a0, aAdr1[0] + kOffA);
            ldm4(a1, aAdr1[1] + kOffA);
            ldm4(bb, bAdr1[0] + kOffB);
            mma16(acc[0][0], a0, bb[0], bb[1]);
            mma16(acc[1][0], a1, bb[0], bb[1]);
            mma16(acc[0][1], a0, bb[2], bb[3]);
            mma16(acc[1][1], a1, bb[2], bb[3]);
            ldm4(bb, bAdr1[1] + kOffB);
            mma16(acc[0][2], a0, bb[0], bb[1]);
            mma16(acc[1][2], a1, bb[0], bb[1]);
            mma16(acc[0][3], a0, bb[2], bb[3]);
            mma16(acc[1][3], a1, bb[2], bb[3]);
        }
        __syncthreads();   // W1 dead -> region becomes P16

        // ---- epilogue 1 (register-local gating) ----
        #pragma unroll
        for (int ni = 0; ni < 2; ni++) {
            int c0 = 16 * wn + 8 * ni + 2 * t;
            float sb0 = __ldg(sig_b  + iblk * 64 + c0);
            float sb1 = __ldg(sig_b  + iblk * 64 + c0 + 1);
            float gb0 = __ldg(gate_b + iblk * 64 + c0);
            float gb1 = __ldg(gate_b + iblk * 64 + c0 + 1);
            #pragma unroll
            for (int mi = 0; mi < 2; mi++) {
                int r = 32 * wm + 16 * mi + g;
                float p00 = fmaxf(acc[mi][ni][0] + sb0, 0.f) * sigm(acc[mi][ni + 2][0] + gb0);
                float p01 = fmaxf(acc[mi][ni][1] + sb1, 0.f) * sigm(acc[mi][ni + 2][1] + gb1);
                float p10 = fmaxf(acc[mi][ni][2] + sb0, 0.f) * sigm(acc[mi][ni + 2][2] + gb0);
                float p11 = fmaxf(acc[mi][ni][3] + sb1, 0.f) * sigm(acc[mi][ni + 2][3] + gb1);
                P16u[r * P_STRW + (c0 >> 1)]       = packh2(p00, p01);
                P16u[(r + 8) * P_STRW + (c0 >> 1)] = packh2(p10, p11);
            }
        }
        __syncthreads();

        // ---- GEMM2: D2[128m][64n] = P16 x W2^T ----
        float acc2[2][2][4];
        #pragma unroll
        for (int mi = 0; mi < 2; mi++)
            #pragma unroll
            for (int ni = 0; ni < 2; ni++)
                #pragma unroll
                for (int q = 0; q < 4; q++) acc2[mi][ni][q] = 0.f;

        #pragma unroll
        for (int kt = 0; kt < 4; kt++) {
            uint32_t a0[4], a1[4], bb[4];
            ldm4(a0, aAdr2base + kt * 32);
            ldm4(a1, aAdr2base + 16 * P_STRB + kt * 32);
            ldm4(bb, bAdr2 + kt * 32);
            mma16(acc2[0][0], a0, bb[0], bb[1]);
            mma16(acc2[1][0], a1, bb[0], bb[1]);
            mma16(acc2[0][1], a0, bb[2], bb[3]);
            mma16(acc2[1][1], a1, bb[2], bb[3]);
        }
        __syncthreads();   // P16 / W2 dead -> stage next weights async

        if (iblk + 1 < NBLK) {
            for (int idx = tid; idx < 2176; idx += NTH)
                cp16(smem_s + idx * 16, &wpre1[iblk + 1][0] + idx * 8);
            for (int idx = tid; idx < 576; idx += NTH)
                cp16(smem_s + W2_OFFB + idx * 16, &wpre2[iblk + 1][0] + idx * 8);
        } else {
            for (int idx = tid; idx < 1088; idx += NTH)
                cp16(smem_s + idx * 16, wpre3 + idx * 8);
        }
        CP_COMMIT();

        // ---- epilogue 2: residual update (overlapped with cp.async) ----
        const float* obp = out_b + iblk * 64;
        #pragma unroll
        for (int mi = 0; mi < 2; mi++)
            #pragma unroll
            for (int ni = 0; ni < 2; ni++) {
                int r0 = 32 * wm + 16 * mi + g;
                int c0 = 16 * wn + 8 * ni + 2 * t;
                float ob0 = __ldg(obp + c0);
                float ob1 = __ldg(obp + c0 + 1);
                float2* gp0 = (float2*)(G + (r0 + 1) * G_STRF + c0);
                float2* gp1 = (float2*)(G + (r0 + 9) * G_STRF + c0);
                float2 o0 = *gp0, o1 = *gp1;
                float v00 = acc2[mi][ni][0] + ob0 + o0.x;
                float v01 = acc2[mi][ni][1] + ob1 + o0.y;
                float v10 = acc2[mi][ni][2] + ob0 + o1.x;
                float v11 = acc2[mi][ni][3] + ob1 + o1.y;
                if (tbase + r0 < 0)     { v00 = 0.f; v01 = 0.f; }
                if (tbase + r0 + 8 < 0) { v10 = 0.f; v11 = 0.f; }
                *gp0 = make_float2(v00, v01);
                *gp1 = make_float2(v10, v11);
                G16u[(r0 + 1) * P_STRW + (c0 >> 1)] = packh2(v00, v01);
                G16u[(r0 + 9) * P_STRW + (c0 >> 1)] = packh2(v10, v11);
            }
        CP_WAIT0();
        __syncthreads();
    }

    // ================= skip (last timestep, last chunk only) =================
    if (chunk == NCHUNK - 1 && tid < 64) {
        int qs = (TLEN - 1) - tbase + 1;   // G row holding t=4095 (=9)
        float acc = __ldg(skip_b + tid);
        #pragma unroll 8
        for (int c = 0; c < 64; c++)
            acc += __ldg(skip_w + tid * 64 + c) * G[qs * G_STRF + c];
        out[(size_t)BATCH * CCH * TOUT + b * 64 + tid] = acc;
    }
    __syncthreads();   // skip's G32 reads done before GD overlays it

    // ---- GD gather: GD[jl][tap*64+c] = G16[2jl+5+tap][c], 272B rows ----
    for (int idx = tid; idx < 4096; idx += NTH) {
        int jl = idx >> 6, kw = idx & 63;
        int tap = kw >> 5, cw = kw & 31;
        int q = 2 * jl + 5 + tap;
        if (q > 128) q = 128;
        GDu[jl * GD_STRW + kw] = G16u[q * P_STRW + cw];
    }
    __syncthreads();

    // ================= dilated stride-2 conv (GEMM3, M=64) =================
    const int wm3 = w >> 3;
    const int wn3 = w & 7;
    const uint32_t bAdr3 = smem_s + (8 * wn3 + lmrow) * W1_STRB + matLo * 16;
    uint32_t aAdr3[2];
    #pragma unroll
    for (int mi = 0; mi < 2; mi++)
        aAdr3[mi] = smem_s + GD_OFFB
                  + (32 * wm3 + 16 * mi + matLo * 8 + lmrow) * W1_STRB + matHi * 16;

    float acc3[2][4];
    #pragma unroll
    for (int mi = 0; mi < 2; mi++)
        #pragma unroll
        for (int q = 0; q < 4; q++) acc3[mi][q] = 0.f;

    #pragma unroll
    for (int kt = 0; kt < 8; kt++) {
        uint32_t a0[4], a1[4], b0, b1;
        ldm4(a0, aAdr3[0] + kt * 32);
        ldm4(a1, aAdr3[1] + kt * 32);
        ldm2(b0, b1, bAdr3 + kt * 32);
        mma16(acc3[0], a0, b0, b1);
        mma16(acc3[1], a1, b0, b1);
    }

    // epilogue 3: transpose through SD, then coalesced stores
    {
        int cc0 = 8 * wn3 + 2 * t;
        float db0 = __ldg(dil_b + cc0);
        float db1 = __ldg(dil_b + cc0 + 1);
        #pragma unroll
        for (int mi = 0; mi < 2; mi++) {
            int jl0 = 32 * wm3 + 16 * mi + g;
            if (jl0 < JC) {
                SD[cc0 * SD_STRF + jl0]       = acc3[mi][0] + db0;
                SD[(cc0 + 1) * SD_STRF + jl0] = acc3[mi][1] + db1;
            }
            int jl1 = jl0 + 8;
            if (jl1 < JC) {
                SD[cc0 * SD_STRF + jl1]       = acc3[mi][2] + db0;
                SD[(cc0 + 1) * SD_STRF + jl1] = acc3[mi][3] + db1;
            }
        }
    }
    __syncthreads();

    float* outb = out + (size_t)b * CCH * TOUT;
    #pragma unroll
    for (int cc = 0; cc < 4; cc++) {
        int c = 4 * w + cc;
        for (int jl = l; jl < JC; jl += 32) {
            int j = j0 + jl;
            if (j < TOUT) outb[c * TOUT + j] = SD[c * SD_STRF + jl];
        }
    }
}

extern "C" void kernel_launch(void* const* d_in, const int* in_sizes, int n_in,
                              void* d_out, int out_size)
{
    (void)in_sizes; (void)n_in; (void)out_size;
    const float* x      = (const float*)d_in[0];
    const float* sig_w  = (const float*)d_in[1];
    const float* sig_b  = (const float*)d_in[2];
    const float* gate_w = (const float*)d_in[3];
    const float* gate_b = (const float*)d_in[4];
    const float* out_w  = (const float*)d_in[5];
    const float* out_b  = (const float*)d_in[6];
    const float* skip_w = (const float*)d_in[7];
    const float* skip_b = (const float*)d_in[8];
    const float* dil_w  = (const float*)d_in[9];
    const float* dil_b  = (const float*)d_in[10];
    float* out = (float*)d_out;

    prep_weights<<<96, 256>>>(sig_w, gate_w, out_w, dil_w);

    cudaFuncSetAttribute(wavenet_h16_kernel,
                         cudaFuncAttributeMaxDynamicSharedMemorySize, SMEM_BYTES);
    dim3 grid(NCHUNK, BATCH, 1);
    wavenet_h16_kernel<<<grid, NTH, SMEM_BYTES>>>(
        x, sig_b, gate_b, out_b, skip_w, skip_b, dil_b, out);
}

// round 15
// speedup vs baseline: 1.5279x; 1.1339x over previous
#include <cuda_runtime.h>
#include <cuda_fp16.h>
#include <cstdint>

// Problem constants
#define BATCH 256
#define CCH   64
#define TLEN  4096
#define NBLK  4
#define TOUT  2048
#define JC    62
#define NCHUNK 34        // ceil(2048/62)
#define NTH   512

// ---- SMEM byte layout (97696 B -> 2 CTAs/SM, ~38KB L1D carveout) ----
// REG [0, 34816): W1 fp16 [128][272B] (GEMM1) / W3 fp16 [64][272B] (GEMM3)
//   + SD fp32 [64][68f] at byte 17408 (epilogue 3). P16 fp16 [128][144B]
//   overlays REG at byte 0 after GEMM1.
// W2 fp16 [64][144B] at byte 34816
// G32 fp32 [129][68f] at byte 44032; GD16 fp16 [64][272B] overlays (dilated)
// G16 fp16 [129][144B] at byte 79120
#define W1_STRB 272
#define P_STRB  144
#define P_STRW  36
#define W2_OFFB 34816
#define SD_OFFF 4352
#define SD_STRF 68
#define G32_OFFF 11008
#define G_STRF  68
#define GD_OFFB 44032
#define GD_STRW 68
#define G16_OFFB 79120
#define G16_OFFH 39560
#define G16_STRB 144
#define G16_STRH 72
#define SMEM_BYTES 97696

// Pre-converted fp16 weights in SMEM row layout
__device__ __align__(16) __half wpre1[NBLK][128 * 136];  // sig/gate interleaved
__device__ __align__(16) __half wpre2[NBLK][64 * 72];    // out_w
__device__ __align__(16) __half wpre3[64 * 136];         // dil_w

__global__ void __launch_bounds__(256)
prep_weights(const float* __restrict__ sig_w, const float* __restrict__ gate_w,
             const float* __restrict__ out_w, const float* __restrict__ dil_w)
{
    int tid0 = blockIdx.x * 256 + threadIdx.x;
    int nth  = gridDim.x * 256;
    for (int idx = tid0; idx < NBLK * 128 * 128; idx += nth) {
        int iblk = idx >> 14, r = (idx >> 7) & 127, k = idx & 127;
        int wn = r >> 5, rr = r & 31;
        int h  = 16 * wn + (rr & 15);
        const float* src = (rr < 16 ? sig_w : gate_w) + iblk * 8192;
        wpre1[iblk][r * 136 + k] = __float2half(src[h * 128 + (k & 63) * 2 + (k >> 6)]);
    }
    for (int idx = tid0; idx < NBLK * 64 * 64; idx += nth) {
        int iblk = idx >> 12, c = (idx >> 6) & 63, h = idx & 63;
        wpre2[iblk][c * 72 + h] = __float2half(out_w[iblk * 4096 + c * 64 + h]);
    }
    for (int idx = tid0; idx < 64 * 128; idx += nth) {
        int cc = idx >> 7, k = idx & 127;
        wpre3[cc * 136 + k] = __float2half(dil_w[cc * 128 + (k & 63) * 2 + (k >> 6)]);
    }
}

__device__ __forceinline__ uint32_t packh2(float lo, float hi) {
    __half2 h = __floats2half2_rn(lo, hi);
    return *reinterpret_cast<uint32_t*>(&h);
}
// sigmoid via single-MUFU tanh.approx: sigmoid(x) = 0.5*tanh(x/2) + 0.5
__device__ __forceinline__ float sigm(float v) {
    float th;
    asm("tanh.approx.f32 %0, %1;" : "=f"(th) : "f"(v * 0.5f));
    return fmaf(0.5f, th, 0.5f);
}
__device__ __forceinline__ void mma16(float d[4], const uint32_t a[4],
                                      uint32_t b0, uint32_t b1) {
    asm volatile(
        "mma.sync.aligned.m16n8k16.row.col.f32.f16.f16.f32 "
        "{%0,%1,%2,%3}, {%4,%5,%6,%7}, {%8,%9}, {%0,%1,%2,%3};"
        : "+f"(d[0]), "+f"(d[1]), "+f"(d[2]), "+f"(d[3])
        : "r"(a[0]), "r"(a[1]), "r"(a[2]), "r"(a[3]), "r"(b0), "r"(b1));
}
__device__ __forceinline__ void ldm4(uint32_t r[4], uint32_t addr) {
    asm volatile("ldmatrix.sync.aligned.m8n8.x4.shared.b16 {%0,%1,%2,%3}, [%4];"
        : "=r"(r[0]), "=r"(r[1]), "=r"(r[2]), "=r"(r[3]) : "r"(addr));
}
__device__ __forceinline__ void ldm2(uint32_t& r0, uint32_t& r1, uint32_t addr) {
    asm volatile("ldmatrix.sync.aligned.m8n8.x2.shared.b16 {%0,%1}, [%2];"
        : "=r"(r0), "=r"(r1) : "r"(addr));
}
__device__ __forceinline__ void cp16(uint32_t dst, const __half* src) {
    asm volatile("cp.async.cg.shared.global [%0], [%1], 16;"
        :: "r"(dst), "l"(__cvta_generic_to_global(src)));
}
#define CP_COMMIT() asm volatile("cp.async.commit_group;" ::: "memory")
#define CP_WAIT0()  asm volatile("cp.async.wait_group 0;" ::: "memory")

__global__ void __launch_bounds__(NTH, 2)
wavenet_h16_kernel(const float* __restrict__ x,
                   const float* __restrict__ sig_b, const float* __restrict__ gate_b,
                   const float* __restrict__ out_b,
                   const float* __restrict__ skip_w, const float* __restrict__ skip_b,
                   const float* __restrict__ dil_b,
                   float* __restrict__ out)
{
    extern __shared__ float sm[];
    uint32_t* P16u = (uint32_t*)sm;           // overlays W1 after GEMM1
    float*    SD   = sm + SD_OFFF;
    float*    G    = sm + G32_OFFF;
    uint32_t* GDu  = (uint32_t*)((char*)sm + GD_OFFB);
    __half*   G16h = (__half*)sm + G16_OFFH;
    uint32_t* G16u = (uint32_t*)((char*)sm + G16_OFFB);

    const uint32_t smem_s = (uint32_t)__cvta_generic_to_shared(sm);

    const int tid = threadIdx.x;
    const int w   = tid >> 5;
    const int l   = tid & 31;
    const int g   = l >> 2;
    const int t   = l & 3;
    const int wm  = w >> 2;        // m-block (rows 32*wm..+32)
    const int wn  = w & 3;         // n-block: channels 16*wn..+16 (sig+gate)
    const int matLo = (l >> 3) & 1;
    const int matHi = l >> 4;
    const int lmrow = l & 7;

    const int b     = blockIdx.y;
    const int chunk = blockIdx.x;
    const int j0    = chunk * JC;
    const int tbase = 2 * j0 - 5;

    // ---- prologue: stage W1(0)+W2(0) via cp.async, overlapped with x-load ----
    for (int idx = tid; idx < 2176; idx += NTH)
        cp16(smem_s + idx * 16, &wpre1[0][0] + idx * 8);
    for (int idx = tid; idx < 576; idx += NTH)
        cp16(smem_s + W2_OFFB + idx * 16, &wpre2[0][0] + idx * 8);
    CP_COMMIT();

    // ---- load x tile into G32 and G16 ----
    const float* xb = x + (size_t)b * CCH * TLEN;
    for (int c = w; c < CCH; c += 16) {
        const float* xc = xb + c * TLEN;
        for (int q = l; q < 129; q += 32) {
            int tt = tbase + q - 1;
            float v = (tt >= 0 && tt < TLEN) ? xc[tt] : 0.f;
            G[q * G_STRF + c] = v;
            G16h[q * G16_STRH + c] = __float2half(v);
        }
    }
    CP_WAIT0();
    __syncthreads();

    // ldmatrix base addresses
    uint32_t aAdr1[2];
    #pragma unroll
    for (int mi = 0; mi < 2; mi++)
        aAdr1[mi] = smem_s + G16_OFFB
                  + (32 * wm + 16 * mi + matLo * 8 + lmrow) * G16_STRB + matHi * 16;
    uint32_t bAdr1[2];
    #pragma unroll
    for (int p = 0; p < 2; p++)
        bAdr1[p] = smem_s + (32 * wn + 16 * p + matHi * 8 + lmrow) * W1_STRB + matLo * 16;
    const uint32_t aAdr2base = smem_s + (32 * wm + matLo * 8 + lmrow) * P_STRB + matHi * 16;
    const uint32_t bAdr2 = smem_s + W2_OFFB
                         + (16 * wn + matHi * 8 + lmrow) * P_STRB + matLo * 16;

    // ================= 4 residual blocks =================
    for (int iblk = 0; iblk < NBLK; iblk++) {
        // ---- GEMM1: D[128m][128n] ; A[m][tap*64+c] = G16[m+tap][c] ----
        float acc[2][4][4];
        #pragma unroll
        for (int mi = 0; mi < 2; mi++)
            #pragma unroll
            for (int ni = 0; ni < 4; ni++)
                #pragma unroll
                for (int q = 0; q < 4; q++) acc[mi][ni][q] = 0.f;

        #pragma unroll
        for (int kt = 0; kt < 8; kt++) {
            const uint32_t kOffA = (kt >> 2) * G16_STRB + (kt & 3) * 32;
            const uint32_t kOffB = kt * 32;
            uint32_t a0[4], a1[4], bb[4];
            ldm4(a0, aAdr1[0] + kOffA);
            ldm4(a1, aAdr1[1] + kOffA);
            ldm4(bb, bAdr1[0] + kOffB);
            mma16(acc[0][0], a0, bb[0], bb[1]);
            mma16(acc[1][0], a1, bb[0], bb[1]);
            mma16(acc[0][1], a0, bb[2], bb[3]);
            mma16(acc[1][1], a1, bb[2], bb[3]);
            ldm4(bb, bAdr1[1] + kOffB);
            mma16(acc[0][2], a0, bb[0], bb[1]);
            mma16(acc[1][2], a1, bb[0], bb[1]);
            mma16(acc[0][3], a0, bb[2], bb[3]);
            mma16(acc[1][3], a1, bb[2], bb[3]);
        }
        __syncthreads();   // W1 dead -> region becomes P16

        // ---- epilogue 1 (register-local gating, tanh-based sigmoid) ----
        #pragma unroll
        for (int ni = 0; ni < 2; ni++) {
            int c0 = 16 * wn + 8 * ni + 2 * t;
            float sb0 = __ldg(sig_b  + iblk * 64 + c0);
            float sb1 = __ldg(sig_b  + iblk * 64 + c0 + 1);
            float gb0 = __ldg(gate_b + iblk * 64 + c0);
            float gb1 = __ldg(gate_b + iblk * 64 + c0 + 1);
            #pragma unroll
            for (int mi = 0; mi < 2; mi++) {
                int r = 32 * wm + 16 * mi + g;
                float p00 = fmaxf(acc[mi][ni][0] + sb0, 0.f) * sigm(acc[mi][ni + 2][0] + gb0);
                float p01 = fmaxf(acc[mi][ni][1] + sb1, 0.f) * sigm(acc[mi][ni + 2][1] + gb1);
                float p10 = fmaxf(acc[mi][ni][2] + sb0, 0.f) * sigm(acc[mi][ni + 2][2] + gb0);
                float p11 = fmaxf(acc[mi][ni][3] + sb1, 0.f) * sigm(acc[mi][ni + 2][3] + gb1);
                P16u[r * P_STRW + (c0 >> 1)]       = packh2(p00, p01);
                P16u[(r + 8) * P_STRW + (c0 >> 1)] = packh2(p10, p11);
            }
        }
        __syncthreads();

        // ---- GEMM2: D2[128m][64n] = P16 x W2^T ----
        float acc2[2][2][4];
        #pragma unroll
        for (int mi = 0; mi < 2; mi++)
            #pragma unroll
            for (int ni = 0; ni < 2; ni++)
                #pragma unroll
                for (int q = 0; q < 4; q++) acc2[mi][ni][q] = 0.f;

        #pragma unroll
        for (int kt = 0; kt < 4; kt++) {
            uint32_t a0[4], a1[4], bb[4];
            ldm4(a0, aAdr2base + kt * 32);
            ldm4(a1, aAdr2base + 16 * P_STRB + kt * 32);
            ldm4(bb, bAdr2 + kt * 32);
            mma16(acc2[0][0], a0, bb[0], bb[1]);
            mma16(acc2[1][0], a1, bb[0], bb[1]);
            mma16(acc2[0][1], a0, bb[2], bb[3]);
            mma16(acc2[1][1], a1, bb[2], bb[3]);
        }
        __syncthreads();   // P16 / W2 dead -> stage next weights async

        if (iblk + 1 < NBLK) {
            for (int idx = tid; idx < 2176; idx += NTH)
                cp16(smem_s + idx * 16, &wpre1[iblk + 1][0] + idx * 8);
            for (int idx = tid; idx < 576; idx += NTH)
                cp16(smem_s + W2_OFFB + idx * 16, &wpre2[iblk + 1][0] + idx * 8);
        } else {
            for (int idx = tid; idx < 1088; idx += NTH)
                cp16(smem_s + idx * 16, wpre3 + idx * 8);
        }
        CP_COMMIT();

        // ---- epilogue 2: residual update (overlapped with cp.async) ----
        const float* obp = out_b + iblk * 64;
        #pragma unroll
        for (int mi = 0; mi < 2; mi++)
            #pragma unroll
            for (int ni = 0; ni < 2; ni++) {
                int r0 = 32 * wm + 16 * mi + g;
                int c0 = 16 * wn + 8 * ni + 2 * t;
                float ob0 = __ldg(obp + c0);
                float ob1 = __ldg(obp + c0 + 1);
                float2* gp0 = (float2*)(G + (r0 + 1) * G_STRF + c0);
                float2* gp1 = (float2*)(G + (r0 + 9) * G_STRF + c0);
                float2 o0 = *gp0, o1 = *gp1;
                float v00 = acc2[mi][ni][0] + ob0 + o0.x;
                float v01 = acc2[mi][ni][1] + ob1 + o0.y;
                float v10 = acc2[mi][ni][2] + ob0 + o1.x;
                float v11 = acc2[mi][ni][3] + ob1 + o1.y;
                if (tbase + r0 < 0)     { v00 = 0.f; v01 = 0.f; }
                if (tbase + r0 + 8 < 0) { v10 = 0.f; v11 = 0.f; }
                *gp0 = make_float2(v00, v01);
                *gp1 = make_float2(v10, v11);
                G16u[(r0 + 1) * P_STRW + (c0 >> 1)] = packh2(v00, v01);
                G16u[(r0 + 9) * P_STRW + (c0 >> 1)] = packh2(v10, v11);
            }
        CP_WAIT0();
        __syncthreads();
    }

    // ================= skip (last timestep, last chunk only) =================
    if (chunk == NCHUNK - 1 && tid < 64) {
        int qs = (TLEN - 1) - tbase + 1;   // G row holding t=4095 (=9)
        float acc = __ldg(skip_b + tid);
        #pragma unroll 8
        for (int c = 0; c < 64; c++)
            acc += __ldg(skip_w + tid * 64 + c) * G[qs * G_STRF + c];
        out[(size_t)BATCH * CCH * TOUT + b * 64 + tid] = acc;
    }
    __syncthreads();   // skip's G32 reads done before GD overlays it

    // ---- GD gather: GD[jl][tap*64+c] = G16[2jl+5+tap][c], 272B rows ----
    for (int idx = tid; idx < 4096; idx += NTH) {
        int jl = idx >> 6, kw = idx & 63;
        int tap = kw >> 5, cw = kw & 31;
        int q = 2 * jl + 5 + tap;
        if (q > 128) q = 128;
        GDu[jl * GD_STRW + kw] = G16u[q * P_STRW + cw];
    }
    __syncthreads();

    // ================= dilated stride-2 conv (GEMM3, M=64) =================
    const int wm3 = w >> 3;
    const int wn3 = w & 7;
    const uint32_t bAdr3 = smem_s + (8 * wn3 + lmrow) * W1_STRB + matLo * 16;
    uint32_t aAdr3[2];
    #pragma unroll
    for (int mi = 0; mi < 2; mi++)
        aAdr3[mi] = smem_s + GD_OFFB
                  + (32 * wm3 + 16 * mi + matLo * 8 + lmrow) * W1_STRB + matHi * 16;

    float acc3[2][4];
    #pragma unroll
    for (int mi = 0; mi < 2; mi++)
        #pragma unroll
        for (int q = 0; q < 4; q++) acc3[mi][q] = 0.f;

    #pragma unroll
    for (int kt = 0; kt < 8; kt++) {
        uint32_t a0[4], a1[4], b0, b1;
        ldm4(a0, aAdr3[0] + kt * 32);
        ldm4(a1, aAdr3[1] + kt * 32);
        ldm2(b0, b1, bAdr3 + kt * 32);
        mma16(acc3[0], a0, b0, b1);
        mma16(acc3[1], a1, b0, b1);
    }

    // epilogue 3: transpose through SD, then coalesced stores
    {
        int cc0 = 8 * wn3 + 2 * t;
        float db0 = __ldg(dil_b + cc0);
        float db1 = __ldg(dil_b + cc0 + 1);
        #pragma unroll
        for (int mi = 0; mi < 2; mi++) {
            int jl0 = 32 * wm3 + 16 * mi + g;
            if (jl0 < JC) {
                SD[cc0 * SD_STRF + jl0]       = acc3[mi][0] + db0;
                SD[(cc0 + 1) * SD_STRF + jl0] = acc3[mi][1] + db1;
            }
            int jl1 = jl0 + 8;
            if (jl1 < JC) {
                SD[cc0 * SD_STRF + jl1]       = acc3[mi][2] + db0;
                SD[(cc0 + 1) * SD_STRF + jl1] = acc3[mi][3] + db1;
            }
        }
    }
    __syncthreads();

    float* outb = out + (size_t)b * CCH * TOUT;
    #pragma unroll
    for (int cc = 0; cc < 4; cc++) {
        int c = 4 * w + cc;
        for (int jl = l; jl < JC; jl += 32) {
            int j = j0 + jl;
            if (j < TOUT) outb[c * TOUT + j] = SD[c * SD_STRF + jl];
        }
    }
}

extern "C" void kernel_launch(void* const* d_in, const int* in_sizes, int n_in,
                              void* d_out, int out_size)
{
    (void)in_sizes; (void)n_in; (void)out_size;
    const float* x      = (const float*)d_in[0];
    const float* sig_w  = (const float*)d_in[1];
    const float* sig_b  = (const float*)d_in[2];
    const float* gate_w = (const float*)d_in[3];
    const float* gate_b = (const float*)d_in[4];
    const float* out_w  = (const float*)d_in[5];
    const float* out_b  = (const float*)d_in[6];
    const float* skip_w = (const float*)d_in[7];
    const float* skip_b = (const float*)d_in[8];
    const float* dil_w  = (const float*)d_in[9];
    const float* dil_b  = (const float*)d_in[10];
    float* out = (float*)d_out;

    prep_weights<<<96, 256>>>(sig_w, gate_w, out_w, dil_w);

    cudaFuncSetAttribute(wavenet_h16_kernel,
                         cudaFuncAttributeMaxDynamicSharedMemorySize, SMEM_BYTES);
    dim3 grid(NCHUNK, BATCH, 1);
    wavenet_h16_kernel<<<grid, NTH, SMEM_BYTES>>>(
        x, sig_b, gate_b, out_b, skip_w, skip_b, dil_b, out);
}

// round 16
// speedup vs baseline: 1.6012x; 1.0480x over previous
#include <cuda_runtime.h>
#include <cuda_fp16.h>
#include <cstdint>

// Problem constants
#define BATCH 256
#define CCH   64
#define TLEN  4096
#define NBLK  4
#define TOUT  2048
#define JC    62
#define NCHUNK 34        // ceil(2048/62)
#define NTH   512

// ---- SMEM byte layout (99760 B -> 2 CTAs/SM, ~28KB L1D carveout) ----
// REG [0, 34816): W1 fp16 [128][272B] (GEMM1) / W3 fp16 [64][272B] (GEMM3)
//   + SD fp32 [64][68f] at byte 17408 (epilogue 3). P16 fp16 [128][144B]
//   overlays REG at byte 0 after GEMM1.
// W2 fp16 [64][144B] at byte 34816
// G32 fp32 [129][72f] at byte 44032 (stride 72: 8g+2t residues -> conflict-free
//   float2 epi2 access); GD16 fp16 [64][272B] overlays (dilated)
// G16 fp16 [129][144B] at byte 81184
#define W1_STRB 272
#define P_STRB  144
#define P_STRW  36
#define W2_OFFB 34816
#define SD_OFFF 4352
#define SD_STRF 68
#define G32_OFFF 11008
#define G_STRF  72
#define GD_OFFB 44032
#define GD_STRW 68
#define G16_OFFB 81184
#define G16_OFFH 40592
#define G16_STRB 144
#define G16_STRH 72
#define SMEM_BYTES 99760

// Pre-converted fp16 weights in SMEM row layout
__device__ __align__(16) __half wpre1[NBLK][128 * 136];  // sig/gate interleaved
__device__ __align__(16) __half wpre2[NBLK][64 * 72];    // out_w
__device__ __align__(16) __half wpre3[64 * 136];         // dil_w

__global__ void __launch_bounds__(256)
prep_weights(const float* __restrict__ sig_w, const float* __restrict__ gate_w,
             const float* __restrict__ out_w, const float* __restrict__ dil_w)
{
    int tid0 = blockIdx.x * 256 + threadIdx.x;
    int nth  = gridDim.x * 256;
    for (int idx = tid0; idx < NBLK * 128 * 128; idx += nth) {
        int iblk = idx >> 14, r = (idx >> 7) & 127, k = idx & 127;
        int wn = r >> 5, rr = r & 31;
        int h  = 16 * wn + (rr & 15);
        const float* src = (rr < 16 ? sig_w : gate_w) + iblk * 8192;
        wpre1[iblk][r * 136 + k] = __float2half(src[h * 128 + (k & 63) * 2 + (k >> 6)]);
    }
    for (int idx = tid0; idx < NBLK * 64 * 64; idx += nth) {
        int iblk = idx >> 12, c = (idx >> 6) & 63, h = idx & 63;
        wpre2[iblk][c * 72 + h] = __float2half(out_w[iblk * 4096 + c * 64 + h]);
    }
    for (int idx = tid0; idx < 64 * 128; idx += nth) {
        int cc = idx >> 7, k = idx & 127;
        wpre3[cc * 136 + k] = __float2half(dil_w[cc * 128 + (k & 63) * 2 + (k >> 6)]);
    }
}

__device__ __forceinline__ uint32_t packh2(float lo, float hi) {
    __half2 h = __floats2half2_rn(lo, hi);
    return *reinterpret_cast<uint32_t*>(&h);
}
// sigmoid via single-MUFU tanh.approx: sigmoid(x) = 0.5*tanh(x/2) + 0.5
__device__ __forceinline__ float sigm(float v) {
    float th;
    asm("tanh.approx.f32 %0, %1;" : "=f"(th) : "f"(v * 0.5f));
    return fmaf(0.5f, th, 0.5f);
}
__device__ __forceinline__ void mma16(float d[4], const uint32_t a[4],
                                      uint32_t b0, uint32_t b1) {
    asm volatile(
        "mma.sync.aligned.m16n8k16.row.col.f32.f16.f16.f32 "
        "{%0,%1,%2,%3}, {%4,%5,%6,%7}, {%8,%9}, {%0,%1,%2,%3};"
        : "+f"(d[0]), "+f"(d[1]), "+f"(d[2]), "+f"(d[3])
        : "r"(a[0]), "r"(a[1]), "r"(a[2]), "r"(a[3]), "r"(b0), "r"(b1));
}
__device__ __forceinline__ void ldm4(uint32_t r[4], uint32_t addr) {
    asm volatile("ldmatrix.sync.aligned.m8n8.x4.shared.b16 {%0,%1,%2,%3}, [%4];"
        : "=r"(r[0]), "=r"(r[1]), "=r"(r[2]), "=r"(r[3]) : "r"(addr));
}
__device__ __forceinline__ void ldm2(uint32_t& r0, uint32_t& r1, uint32_t addr) {
    asm volatile("ldmatrix.sync.aligned.m8n8.x2.shared.b16 {%0,%1}, [%2];"
        : "=r"(r0), "=r"(r1) : "r"(addr));
}
__device__ __forceinline__ void cp16(uint32_t dst, const __half* src) {
    asm volatile("cp.async.cg.shared.global [%0], [%1], 16;"
        :: "r"(dst), "l"(__cvta_generic_to_global(src)));
}
#define CP_COMMIT() asm volatile("cp.async.commit_group;" ::: "memory")
#define CP_WAIT0()  asm volatile("cp.async.wait_group 0;" ::: "memory")

__global__ void __launch_bounds__(NTH, 2)
wavenet_h16_kernel(const float* __restrict__ x,
                   const float* __restrict__ sig_b, const float* __restrict__ gate_b,
                   const float* __restrict__ out_b,
                   const float* __restrict__ skip_w, const float* __restrict__ skip_b,
                   const float* __restrict__ dil_b,
                   float* __restrict__ out)
{
    extern __shared__ float sm[];
    uint32_t* P16u = (uint32_t*)sm;           // overlays W1 after GEMM1
    float*    SD   = sm + SD_OFFF;
    float*    G    = sm + G32_OFFF;
    uint32_t* GDu  = (uint32_t*)((char*)sm + GD_OFFB);
    __half*   G16h = (__half*)sm + G16_OFFH;
    uint32_t* G16u = (uint32_t*)((char*)sm + G16_OFFB);

    const uint32_t smem_s = (uint32_t)__cvta_generic_to_shared(sm);

    const int tid = threadIdx.x;
    const int w   = tid >> 5;
    const int l   = tid & 31;
    const int g   = l >> 2;
    const int t   = l & 3;
    const int wm  = w >> 2;        // m-block (rows 32*wm..+32)
    const int wn  = w & 3;         // n-block: channels 16*wn..+16 (sig+gate)
    const int matLo = (l >> 3) & 1;
    const int matHi = l >> 4;
    const int lmrow = l & 7;

    const int b     = blockIdx.y;
    const int chunk = blockIdx.x;
    const int j0    = chunk * JC;
    const int tbase = 2 * j0 - 5;

    // ---- prologue: stage W1(0)+W2(0) via cp.async, overlapped with x-load ----
    for (int idx = tid; idx < 2176; idx += NTH)
        cp16(smem_s + idx * 16, &wpre1[0][0] + idx * 8);
    for (int idx = tid; idx < 576; idx += NTH)
        cp16(smem_s + W2_OFFB + idx * 16, &wpre2[0][0] + idx * 8);
    CP_COMMIT();

    // ---- load x tile into G32 and G16 ----
    const float* xb = x + (size_t)b * CCH * TLEN;
    for (int c = w; c < CCH; c += 16) {
        const float* xc = xb + c * TLEN;
        for (int q = l; q < 129; q += 32) {
            int tt = tbase + q - 1;
            float v = (tt >= 0 && tt < TLEN) ? xc[tt] : 0.f;
            G[q * G_STRF + c] = v;
            G16h[q * G16_STRH + c] = __float2half(v);
        }
    }
    CP_WAIT0();
    __syncthreads();

    // ldmatrix base addresses
    uint32_t aAdr1[2];
    #pragma unroll
    for (int mi = 0; mi < 2; mi++)
        aAdr1[mi] = smem_s + G16_OFFB
                  + (32 * wm + 16 * mi + matLo * 8 + lmrow) * G16_STRB + matHi * 16;
    uint32_t bAdr1[2];
    #pragma unroll
    for (int p = 0; p < 2; p++)
        bAdr1[p] = smem_s + (32 * wn + 16 * p + matHi * 8 + lmrow) * W1_STRB + matLo * 16;
    const uint32_t aAdr2base = smem_s + (32 * wm + matLo * 8 + lmrow) * P_STRB + matHi * 16;
    const uint32_t bAdr2 = smem_s + W2_OFFB
                         + (16 * wn + matHi * 8 + lmrow) * P_STRB + matLo * 16;

    // ================= 4 residual blocks =================
    for (int iblk = 0; iblk < NBLK; iblk++) {
        // ---- GEMM1: D[128m][128n] ; A[m][tap*64+c] = G16[m+tap][c] ----
        float acc[2][4][4];
        #pragma unroll
        for (int mi = 0; mi < 2; mi++)
            #pragma unroll
            for (int ni = 0; ni < 4; ni++)
                #pragma unroll
                for (int q = 0; q < 4; q++) acc[mi][ni][q] = 0.f;

        #pragma unroll
        for (int kt = 0; kt < 8; kt++) {
            const uint32_t kOffA = (kt >> 2) * G16_STRB + (kt & 3) * 32;
            const uint32_t kOffB = kt * 32;
            uint32_t a0[4], a1[4], bb[4];
            ldm4(a0, aAdr1[0] + kOffA);
            ldm4(a1, aAdr1[1] + kOffA);
            ldm4(bb, bAdr1[0] + kOffB);
            mma16(acc[0][0], a0, bb[0], bb[1]);
            mma16(acc[1][0], a1, bb[0], bb[1]);
            mma16(acc[0][1], a0, bb[2], bb[3]);
            mma16(acc[1][1], a1, bb[2], bb[3]);
            ldm4(bb, bAdr1[1] + kOffB);
            mma16(acc[0][2], a0, bb[0], bb[1]);
            mma16(acc[1][2], a1, bb[0], bb[1]);
            mma16(acc[0][3], a0, bb[2], bb[3]);
            mma16(acc[1][3], a1, bb[2], bb[3]);
        }
        __syncthreads();   // W1 dead -> region becomes P16

        // ---- epilogue 1 (register-local gating, tanh-based sigmoid) ----
        #pragma unroll
        for (int ni = 0; ni < 2; ni++) {
            int c0 = 16 * wn + 8 * ni + 2 * t;
            float2 sb = __ldg((const float2*)(sig_b  + iblk * 64 + c0));
            float2 gb = __ldg((const float2*)(gate_b + iblk * 64 + c0));
            #pragma unroll
            for (int mi = 0; mi < 2; mi++) {
                int r = 32 * wm + 16 * mi + g;
                float p00 = fmaxf(acc[mi][ni][0] + sb.x, 0.f) * sigm(acc[mi][ni + 2][0] + gb.x);
                float p01 = fmaxf(acc[mi][ni][1] + sb.y, 0.f) * sigm(acc[mi][ni + 2][1] + gb.y);
                float p10 = fmaxf(acc[mi][ni][2] + sb.x, 0.f) * sigm(acc[mi][ni + 2][2] + gb.x);
                float p11 = fmaxf(acc[mi][ni][3] + sb.y, 0.f) * sigm(acc[mi][ni + 2][3] + gb.y);
                P16u[r * P_STRW + (c0 >> 1)]       = packh2(p00, p01);
                P16u[(r + 8) * P_STRW + (c0 >> 1)] = packh2(p10, p11);
            }
        }
        __syncthreads();

        // ---- GEMM2: D2[128m][64n] = P16 x W2^T ----
        float acc2[2][2][4];
        #pragma unroll
        for (int mi = 0; mi < 2; mi++)
            #pragma unroll
            for (int ni = 0; ni < 2; ni++)
                #pragma unroll
                for (int q = 0; q < 4; q++) acc2[mi][ni][q] = 0.f;

        #pragma unroll
        for (int kt = 0; kt < 4; kt++) {
            uint32_t a0[4], a1[4], bb[4];
            ldm4(a0, aAdr2base + kt * 32);
            ldm4(a1, aAdr2base + 16 * P_STRB + kt * 32);
            ldm4(bb, bAdr2 + kt * 32);
            mma16(acc2[0][0], a0, bb[0], bb[1]);
            mma16(acc2[1][0], a1, bb[0], bb[1]);
            mma16(acc2[0][1], a0, bb[2], bb[3]);
            mma16(acc2[1][1], a1, bb[2], bb[3]);
        }
        __syncthreads();   // P16 / W2 dead -> stage next weights async

        if (iblk + 1 < NBLK) {
            for (int idx = tid; idx < 2176; idx += NTH)
                cp16(smem_s + idx * 16, &wpre1[iblk + 1][0] + idx * 8);
            for (int idx = tid; idx < 576; idx += NTH)
                cp16(smem_s + W2_OFFB + idx * 16, &wpre2[iblk + 1][0] + idx * 8);
        } else {
            for (int idx = tid; idx < 1088; idx += NTH)
                cp16(smem_s + idx * 16, wpre3 + idx * 8);
        }
        CP_COMMIT();

        // ---- epilogue 2: residual update (overlapped with cp.async) ----
        const float* obp = out_b + iblk * 64;
        #pragma unroll
        for (int mi = 0; mi < 2; mi++)
            #pragma unroll
            for (int ni = 0; ni < 2; ni++) {
                int r0 = 32 * wm + 16 * mi + g;
                int c0 = 16 * wn + 8 * ni + 2 * t;
                float2 ob = __ldg((const float2*)(obp + c0));
                float2* gp0 = (float2*)(G + (r0 + 1) * G_STRF + c0);
                float2* gp1 = (float2*)(G + (r0 + 9) * G_STRF + c0);
                float2 o0 = *gp0, o1 = *gp1;
                float v00 = acc2[mi][ni][0] + ob.x + o0.x;
                float v01 = acc2[mi][ni][1] + ob.y + o0.y;
                float v10 = acc2[mi][ni][2] + ob.x + o1.x;
                float v11 = acc2[mi][ni][3] + ob.y + o1.y;
                if (tbase + r0 < 0)     { v00 = 0.f; v01 = 0.f; }
                if (tbase + r0 + 8 < 0) { v10 = 0.f; v11 = 0.f; }
                *gp0 = make_float2(v00, v01);
                *gp1 = make_float2(v10, v11);
                G16u[(r0 + 1) * P_STRW + (c0 >> 1)] = packh2(v00, v01);
                G16u[(r0 + 9) * P_STRW + (c0 >> 1)] = packh2(v10, v11);
            }
        CP_WAIT0();
        __syncthreads();
    }

    // ================= skip (last timestep, last chunk only) =================
    if (chunk == NCHUNK - 1 && tid < 64) {
        int qs = (TLEN - 1) - tbase + 1;   // G row holding t=4095 (=9)
        float acc = __ldg(skip_b + tid);
        #pragma unroll 8
        for (int c = 0; c < 64; c++)
            acc += __ldg(skip_w + tid * 64 + c) * G[qs * G_STRF + c];
        out[(size_t)BATCH * CCH * TOUT + b * 64 + tid] = acc;
    }
    __syncthreads();   // skip's G32 reads done before GD overlays it

    // ---- GD gather: GD[jl][tap*64+c] = G16[2jl+5+tap][c], 272B rows ----
    for (int idx = tid; idx < 4096; idx += NTH) {
        int jl = idx >> 6, kw = idx & 63;
        int tap = kw >> 5, cw = kw & 31;
        int q = 2 * jl + 5 + tap;
        if (q > 128) q = 128;
        GDu[jl * GD_STRW + kw] = G16u[q * P_STRW + cw];
    }
    __syncthreads();

    // ================= dilated stride-2 conv (GEMM3, M=64) =================
    const int wm3 = w >> 3;
    const int wn3 = w & 7;
    const uint32_t bAdr3 = smem_s + (8 * wn3 + lmrow) * W1_STRB + matLo * 16;
    uint32_t aAdr3[2];
    #pragma unroll
    for (int mi = 0; mi < 2; mi++)
        aAdr3[mi] = smem_s + GD_OFFB
                  + (32 * wm3 + 16 * mi + matLo * 8 + lmrow) * W1_STRB + matHi * 16;

    float acc3[2][4];
    #pragma unroll
    for (int mi = 0; mi < 2; mi++)
        #pragma unroll
        for (int q = 0; q < 4; q++) acc3[mi][q] = 0.f;

    #pragma unroll
    for (int kt = 0; kt < 8; kt++) {
        uint32_t a0[4], a1[4], b0, b1;
        ldm4(a0, aAdr3[0] + kt * 32);
        ldm4(a1, aAdr3[1] + kt * 32);
        ldm2(b0, b1, bAdr3 + kt * 32);
        mma16(acc3[0], a0, b0, b1);
        mma16(acc3[1], a1, b0, b1);
    }

    // epilogue 3: transpose through SD, then coalesced stores
    {
        int cc0 = 8 * wn3 + 2 * t;
        float2 db = __ldg((const float2*)(dil_b + cc0));
        #pragma unroll
        for (int mi = 0; mi < 2; mi++) {
            int jl0 = 32 * wm3 + 16 * mi + g;
            if (jl0 < JC) {
                SD[cc0 * SD_STRF + jl0]       = acc3[mi][0] + db.x;
                SD[(cc0 + 1) * SD_STRF + jl0] = acc3[mi][1] + db.y;
            }
            int jl1 = jl0 + 8;
            if (jl1 < JC) {
                SD[cc0 * SD_STRF + jl1]       = acc3[mi][2] + db.x;
                SD[(cc0 + 1) * SD_STRF + jl1] = acc3[mi][3] + db.y;
            }
        }
    }
    __syncthreads();

    float* outb = out + (size_t)b * CCH * TOUT;
    #pragma unroll
    for (int cc = 0; cc < 4; cc++) {
        int c = 4 * w + cc;
        for (int jl = l; jl < JC; jl += 32) {
            int j = j0 + jl;
            if (j < TOUT) outb[c * TOUT + j] = SD[c * SD_STRF + jl];
        }
    }
}

extern "C" void kernel_launch(void* const* d_in, const int* in_sizes, int n_in,
                              void* d_out, int out_size)
{
    (void)in_sizes; (void)n_in; (void)out_size;
    const float* x      = (const float*)d_in[0];
    const float* sig_w  = (const float*)d_in[1];
    const float* sig_b  = (const float*)d_in[2];
    const float* gate_w = (const float*)d_in[3];
    const float* gate_b = (const float*)d_in[4];
    const float* out_w  = (const float*)d_in[5];
    const float* out_b  = (const float*)d_in[6];
    const float* skip_w = (const float*)d_in[7];
    const float* skip_b = (const float*)d_in[8];
    const float* dil_w  = (const float*)d_in[9];
    const float* dil_b  = (const float*)d_in[10];
    float* out = (float*)d_out;

    prep_weights<<<96, 256>>>(sig_w, gate_w, out_w, dil_w);

    cudaFuncSetAttribute(wavenet_h16_kernel,
                         cudaFuncAttributeMaxDynamicSharedMemorySize, SMEM_BYTES);
    dim3 grid(NCHUNK, BATCH, 1);
    wavenet_h16_kernel<<<grid, NTH, SMEM_BYTES>>>(
        x, sig_b, gate_b, out_b, skip_w, skip_b, dil_b, out);
}

// round 17
// speedup vs baseline: 1.7641x; 1.1017x over previous
#include <cuda_runtime.h>
#include <cuda_fp16.h>
#include <cstdint>

// Problem constants
#define BATCH 256
#define CCH   64
#define TLEN  4096
#define NBLK  4
#define TOUT  2048
#define JC    62
#define NCHUNK 34        // ceil(2048/62)
#define NTH   512

// ---- SMEM byte layout (80016 B -> 2 CTAs/SM, ~68KB L1D carveout) ----
// REG [0, 34816): W1 fp16 [128][272B] (GEMM1) / W3 fp16 [64][272B] (GEMM3)
//   + SD fp32 [64][68f] at byte 17408 (epilogue 3). P16 fp16 [128][144B]
//   overlays REG at byte 0 after GEMM1.
// W2 fp16 [64][144B] at byte 34816
// GD16 fp16 [64][272B] at byte 44032 (dilated A tile)
// G16 fp16 [129][144B] at byte 61440  (single residual master, fp16)
#define W1_STRB 272
#define P_STRB  144
#define P_STRW  36
#define W2_OFFB 34816
#define SD_OFFF 4352
#define SD_STRF 68
#define GD_OFFB 44032
#define GD_STRW 68
#define G16_OFFB 61440
#define G16_OFFH 30720
#define G16_STRB 144
#define G16_STRH 72
#define G16_STRW 36
#define SMEM_BYTES 80016

// Pre-converted fp16 weights in SMEM row layout
__device__ __align__(16) __half wpre1[NBLK][128 * 136];  // sig/gate interleaved
__device__ __align__(16) __half wpre2[NBLK][64 * 72];    // out_w
__device__ __align__(16) __half wpre3[64 * 136];         // dil_w

__global__ void __launch_bounds__(256)
prep_weights(const float* __restrict__ sig_w, const float* __restrict__ gate_w,
             const float* __restrict__ out_w, const float* __restrict__ dil_w)
{
    int tid0 = blockIdx.x * 256 + threadIdx.x;
    int nth  = gridDim.x * 256;
    for (int idx = tid0; idx < NBLK * 128 * 128; idx += nth) {
        int iblk = idx >> 14, r = (idx >> 7) & 127, k = idx & 127;
        int wn = r >> 5, rr = r & 31;
        int h  = 16 * wn + (rr & 15);
        const float* src = (rr < 16 ? sig_w : gate_w) + iblk * 8192;
        wpre1[iblk][r * 136 + k] = __float2half(src[h * 128 + (k & 63) * 2 + (k >> 6)]);
    }
    for (int idx = tid0; idx < NBLK * 64 * 64; idx += nth) {
        int iblk = idx >> 12, c = (idx >> 6) & 63, h = idx & 63;
        wpre2[iblk][c * 72 + h] = __float2half(out_w[iblk * 4096 + c * 64 + h]);
    }
    for (int idx = tid0; idx < 64 * 128; idx += nth) {
        int cc = idx >> 7, k = idx & 127;
        wpre3[cc * 136 + k] = __float2half(dil_w[cc * 128 + (k & 63) * 2 + (k >> 6)]);
    }
}

__device__ __forceinline__ uint32_t packh2(float lo, float hi) {
    __half2 h = __floats2half2_rn(lo, hi);
    return *reinterpret_cast<uint32_t*>(&h);
}
__device__ __forceinline__ float2 unpackh2(uint32_t v) {
    __half2 h = *reinterpret_cast<__half2*>(&v);
    return __half22float2(h);
}
// sigmoid via single-MUFU tanh.approx: sigmoid(x) = 0.5*tanh(x/2) + 0.5
__device__ __forceinline__ float sigm(float v) {
    float th;
    asm("tanh.approx.f32 %0, %1;" : "=f"(th) : "f"(v * 0.5f));
    return fmaf(0.5f, th, 0.5f);
}
__device__ __forceinline__ void mma16(float d[4], const uint32_t a[4],
                                      uint32_t b0, uint32_t b1) {
    asm volatile(
        "mma.sync.aligned.m16n8k16.row.col.f32.f16.f16.f32 "
        "{%0,%1,%2,%3}, {%4,%5,%6,%7}, {%8,%9}, {%0,%1,%2,%3};"
        : "+f"(d[0]), "+f"(d[1]), "+f"(d[2]), "+f"(d[3])
        : "r"(a[0]), "r"(a[1]), "r"(a[2]), "r"(a[3]), "r"(b0), "r"(b1));
}
__device__ __forceinline__ void ldm4(uint32_t r[4], uint32_t addr) {
    asm volatile("ldmatrix.sync.aligned.m8n8.x4.shared.b16 {%0,%1,%2,%3}, [%4];"
        : "=r"(r[0]), "=r"(r[1]), "=r"(r[2]), "=r"(r[3]) : "r"(addr));
}
__device__ __forceinline__ void ldm2(uint32_t& r0, uint32_t& r1, uint32_t addr) {
    asm volatile("ldmatrix.sync.aligned.m8n8.x2.shared.b16 {%0,%1}, [%2];"
        : "=r"(r0), "=r"(r1) : "r"(addr));
}
__device__ __forceinline__ void cp16(uint32_t dst, const __half* src) {
    asm volatile("cp.async.cg.shared.global [%0], [%1], 16;"
        :: "r"(dst), "l"(__cvta_generic_to_global(src)));
}
#define CP_COMMIT() asm volatile("cp.async.commit_group;" ::: "memory")
#define CP_WAIT0()  asm volatile("cp.async.wait_group 0;" ::: "memory")

__global__ void __launch_bounds__(NTH, 2)
wavenet_h16_kernel(const float* __restrict__ x,
                   const float* __restrict__ sig_b, const float* __restrict__ gate_b,
                   const float* __restrict__ out_b,
                   const float* __restrict__ skip_w, const float* __restrict__ skip_b,
                   const float* __restrict__ dil_b,
                   float* __restrict__ out)
{
    extern __shared__ float sm[];
    uint32_t* P16u = (uint32_t*)sm;           // overlays W1 after GEMM1
    float*    SD   = sm + SD_OFFF;
    uint32_t* GDu  = (uint32_t*)((char*)sm + GD_OFFB);
    __half*   G16h = (__half*)sm + G16_OFFH;
    uint32_t* G16u = (uint32_t*)((char*)sm + G16_OFFB);

    const uint32_t smem_s = (uint32_t)__cvta_generic_to_shared(sm);

    const int tid = threadIdx.x;
    const int w   = tid >> 5;
    const int l   = tid & 31;
    const int g   = l >> 2;
    const int t   = l & 3;
    const int wm  = w >> 2;        // m-block (rows 32*wm..+32)
    const int wn  = w & 3;         // n-block: channels 16*wn..+16 (sig+gate)
    const int matLo = (l >> 3) & 1;
    const int matHi = l >> 4;
    const int lmrow = l & 7;

    const int b     = blockIdx.y;
    const int chunk = blockIdx.x;
    const int j0    = chunk * JC;
    const int tbase = 2 * j0 - 5;

    // ---- prologue: stage W1(0)+W2(0) via cp.async, overlapped with x-load ----
    for (int idx = tid; idx < 2176; idx += NTH)
        cp16(smem_s + idx * 16, &wpre1[0][0] + idx * 8);
    for (int idx = tid; idx < 576; idx += NTH)
        cp16(smem_s + W2_OFFB + idx * 16, &wpre2[0][0] + idx * 8);
    CP_COMMIT();

    // ---- load x tile into G16 (single fp16 residual master) ----
    const float* xb = x + (size_t)b * CCH * TLEN;
    for (int c = w; c < CCH; c += 16) {
        const float* xc = xb + c * TLEN;
        for (int q = l; q < 129; q += 32) {
            int tt = tbase + q - 1;
            float v = (tt >= 0 && tt < TLEN) ? xc[tt] : 0.f;
            G16h[q * G16_STRH + c] = __float2half(v);
        }
    }
    CP_WAIT0();
    __syncthreads();

    // ldmatrix base addresses
    uint32_t aAdr1[2];
    #pragma unroll
    for (int mi = 0; mi < 2; mi++)
        aAdr1[mi] = smem_s + G16_OFFB
                  + (32 * wm + 16 * mi + matLo * 8 + lmrow) * G16_STRB + matHi * 16;
    uint32_t bAdr1[2];
    #pragma unroll
    for (int p = 0; p < 2; p++)
        bAdr1[p] = smem_s + (32 * wn + 16 * p + matHi * 8 + lmrow) * W1_STRB + matLo * 16;
    const uint32_t aAdr2base = smem_s + (32 * wm + matLo * 8 + lmrow) * P_STRB + matHi * 16;
    const uint32_t bAdr2 = smem_s + W2_OFFB
                         + (16 * wn + matHi * 8 + lmrow) * P_STRB + matLo * 16;

    // ================= 4 residual blocks =================
    for (int iblk = 0; iblk < NBLK; iblk++) {
        // ---- GEMM1: D[128m][128n] ; A[m][tap*64+c] = G16[m+tap][c] ----
        float acc[2][4][4];
        #pragma unroll
        for (int mi = 0; mi < 2; mi++)
            #pragma unroll
            for (int ni = 0; ni < 4; ni++)
                #pragma unroll
                for (int q = 0; q < 4; q++) acc[mi][ni][q] = 0.f;

        #pragma unroll
        for (int kt = 0; kt < 8; kt++) {
            const uint32_t kOffA = (kt >> 2) * G16_STRB + (kt & 3) * 32;
            const uint32_t kOffB = kt * 32;
            uint32_t a0[4], a1[4], bb[4];
            ldm4(a0, aAdr1[0] + kOffA);
            ldm4(a1, aAdr1[1] + kOffA);
            ldm4(bb, bAdr1[0] + kOffB);
            mma16(acc[0][0], a0, bb[0], bb[1]);
            mma16(acc[1][0], a1, bb[0], bb[1]);
            mma16(acc[0][1], a0, bb[2], bb[3]);
            mma16(acc[1][1], a1, bb[2], bb[3]);
            ldm4(bb, bAdr1[1] + kOffB);
            mma16(acc[0][2], a0, bb[0], bb[1]);
            mma16(acc[1][2], a1, bb[0], bb[1]);
            mma16(acc[0][3], a0, bb[2], bb[3]);
            mma16(acc[1][3], a1, bb[2], bb[3]);
        }
        __syncthreads();   // W1 dead -> region becomes P16

        // ---- epilogue 1 (register-local gating, tanh-based sigmoid) ----
        #pragma unroll
        for (int ni = 0; ni < 2; ni++) {
            int c0 = 16 * wn + 8 * ni + 2 * t;
            float2 sb = __ldg((const float2*)(sig_b  + iblk * 64 + c0));
            float2 gb = __ldg((const float2*)(gate_b + iblk * 64 + c0));
            #pragma unroll
            for (int mi = 0; mi < 2; mi++) {
                int r = 32 * wm + 16 * mi + g;
                float p00 = fmaxf(acc[mi][ni][0] + sb.x, 0.f) * sigm(acc[mi][ni + 2][0] + gb.x);
                float p01 = fmaxf(acc[mi][ni][1] + sb.y, 0.f) * sigm(acc[mi][ni + 2][1] + gb.y);
                float p10 = fmaxf(acc[mi][ni][2] + sb.x, 0.f) * sigm(acc[mi][ni + 2][2] + gb.x);
                float p11 = fmaxf(acc[mi][ni][3] + sb.y, 0.f) * sigm(acc[mi][ni + 2][3] + gb.y);
                P16u[r * P_STRW + (c0 >> 1)]       = packh2(p00, p01);
                P16u[(r + 8) * P_STRW + (c0 >> 1)] = packh2(p10, p11);
            }
        }
        __syncthreads();

        // ---- GEMM2: D2[128m][64n] = P16 x W2^T ----
        float acc2[2][2][4];
        #pragma unroll
        for (int mi = 0; mi < 2; mi++)
            #pragma unroll
            for (int ni = 0; ni < 2; ni++)
                #pragma unroll
                for (int q = 0; q < 4; q++) acc2[mi][ni][q] = 0.f;

        #pragma unroll
        for (int kt = 0; kt < 4; kt++) {
            uint32_t a0[4], a1[4], bb[4];
            ldm4(a0, aAdr2base + kt * 32);
            ldm4(a1, aAdr2base + 16 * P_STRB + kt * 32);
            ldm4(bb, bAdr2 + kt * 32);
            mma16(acc2[0][0], a0, bb[0], bb[1]);
            mma16(acc2[1][0], a1, bb[0], bb[1]);
            mma16(acc2[0][1], a0, bb[2], bb[3]);
            mma16(acc2[1][1], a1, bb[2], bb[3]);
        }
        __syncthreads();   // P16 / W2 dead -> stage next weights async

        if (iblk + 1 < NBLK) {
            for (int idx = tid; idx < 2176; idx += NTH)
                cp16(smem_s + idx * 16, &wpre1[iblk + 1][0] + idx * 8);
            for (int idx = tid; idx < 576; idx += NTH)
                cp16(smem_s + W2_OFFB + idx * 16, &wpre2[iblk + 1][0] + idx * 8);
        } else {
            for (int idx = tid; idx < 1088; idx += NTH)
                cp16(smem_s + idx * 16, wpre3 + idx * 8);
        }
        CP_COMMIT();

        // ---- epilogue 2: residual update on fp16 master (fp32 math) ----
        const float* obp = out_b + iblk * 64;
        #pragma unroll
        for (int mi = 0; mi < 2; mi++)
            #pragma unroll
            for (int ni = 0; ni < 2; ni++) {
                int r0 = 32 * wm + 16 * mi + g;
                int c0 = 16 * wn + 8 * ni + 2 * t;
                float2 ob = __ldg((const float2*)(obp + c0));
                uint32_t* gp0 = G16u + (r0 + 1) * G16_STRW + (c0 >> 1);
                uint32_t* gp1 = G16u + (r0 + 9) * G16_STRW + (c0 >> 1);
                float2 o0 = unpackh2(*gp0);
                float2 o1 = unpackh2(*gp1);
                float v00 = acc2[mi][ni][0] + ob.x + o0.x;
                float v01 = acc2[mi][ni][1] + ob.y + o0.y;
                float v10 = acc2[mi][ni][2] + ob.x + o1.x;
                float v11 = acc2[mi][ni][3] + ob.y + o1.y;
                if (tbase + r0 < 0)     { v00 = 0.f; v01 = 0.f; }
                if (tbase + r0 + 8 < 0) { v10 = 0.f; v11 = 0.f; }
                *gp0 = packh2(v00, v01);
                *gp1 = packh2(v10, v11);
            }
        CP_WAIT0();
        __syncthreads();
    }

    // ================= skip (last timestep, last chunk only) =================
    if (chunk == NCHUNK - 1 && tid < 64) {
        int qs = (TLEN - 1) - tbase + 1;   // G16 row holding t=4095 (=9)
        float acc = __ldg(skip_b + tid);
        #pragma unroll 8
        for (int c = 0; c < 64; c++)
            acc += __ldg(skip_w + tid * 64 + c) * __half2float(G16h[qs * G16_STRH + c]);
        out[(size_t)BATCH * CCH * TOUT + b * 64 + tid] = acc;
    }

    // ---- GD gather: GD[jl][tap*64+c] = G16[2jl+5+tap][c], 272B rows ----
    for (int idx = tid; idx < 4096; idx += NTH) {
        int jl = idx >> 6, kw = idx & 63;
        int tap = kw >> 5, cw = kw & 31;
        int q = 2 * jl + 5 + tap;
        if (q > 128) q = 128;
        GDu[jl * GD_STRW + kw] = G16u[q * G16_STRW + cw];
    }
    __syncthreads();

    // ================= dilated stride-2 conv (GEMM3, M=64) =================
    const int wm3 = w >> 3;
    const int wn3 = w & 7;
    const uint32_t bAdr3 = smem_s + (8 * wn3 + lmrow) * W1_STRB + matLo * 16;
    uint32_t aAdr3[2];
    #pragma unroll
    for (int mi = 0; mi < 2; mi++)
        aAdr3[mi] = smem_s + GD_OFFB
                  + (32 * wm3 + 16 * mi + matLo * 8 + lmrow) * W1_STRB + matHi * 16;

    float acc3[2][4];
    #pragma unroll
    for (int mi = 0; mi < 2; mi++)
        #pragma unroll
        for (int q = 0; q < 4; q++) acc3[mi][q] = 0.f;

    #pragma unroll
    for (int kt = 0; kt < 8; kt++) {
        uint32_t a0[4], a1[4], b0, b1;
        ldm4(a0, aAdr3[0] + kt * 32);
        ldm4(a1, aAdr3[1] + kt * 32);
        ldm2(b0, b1, bAdr3 + kt * 32);
        mma16(acc3[0], a0, b0, b1);
        mma16(acc3[1], a1, b0, b1);
    }
    __syncthreads();   // P16 region fully dead -> SD overlay safe

    // epilogue 3: transpose through SD, then coalesced stores
    {
        int cc0 = 8 * wn3 + 2 * t;
        float2 db = __ldg((const float2*)(dil_b + cc0));
        #pragma unroll
        for (int mi = 0; mi < 2; mi++) {
            int jl0 = 32 * wm3 + 16 * mi + g;
            if (jl0 < JC) {
                SD[cc0 * SD_STRF + jl0]       = acc3[mi][0] + db.x;
                SD[(cc0 + 1) * SD_STRF + jl0] = acc3[mi][1] + db.y;
            }
            int jl1 = jl0 + 8;
            if (jl1 < JC) {
                SD[cc0 * SD_STRF + jl1]       = acc3[mi][2] + db.x;
                SD[(cc0 + 1) * SD_STRF + jl1] = acc3[mi][3] + db.y;
            }
        }
    }
    __syncthreads();

    float* outb = out + (size_t)b * CCH * TOUT;
    #pragma unroll
    for (int cc = 0; cc < 4; cc++) {
        int c = 4 * w + cc;
        for (int jl = l; jl < JC; jl += 32) {
            int j = j0 + jl;
            if (j < TOUT) outb[c * TOUT + j] = SD[c * SD_STRF + jl];
        }
    }
}

extern "C" void kernel_launch(void* const* d_in, const int* in_sizes, int n_in,
                              void* d_out, int out_size)
{
    (void)in_sizes; (void)n_in; (void)out_size;
    const float* x      = (const float*)d_in[0];
    const float* sig_w  = (const float*)d_in[1];
    const float* sig_b  = (const float*)d_in[2];
    const float* gate_w = (const float*)d_in[3];
    const float* gate_b = (const float*)d_in[4];
    const float* out_w  = (const float*)d_in[5];
    const float* out_b  = (const float*)d_in[6];
    const float* skip_w = (const float*)d_in[7];
    const float* skip_b = (const float*)d_in[8];
    const float* dil_w  = (const float*)d_in[9];
    const float* dil_b  = (const float*)d_in[10];
    float* out = (float*)d_out;

    prep_weights<<<96, 256>>>(sig_w, gate_w, out_w, dil_w);

    cudaFuncSetAttribute(wavenet_h16_kernel,
                         cudaFuncAttributeMaxDynamicSharedMemorySize, SMEM_BYTES);
    dim3 grid(NCHUNK, BATCH, 1);
    wavenet_h16_kernel<<<grid, NTH, SMEM_BYTES>>>(
        x, sig_b, gate_b, out_b, skip_w, skip_b, dil_b, out);
}